// round 13
// baseline (speedup 1.0000x reference)
#include <cuda_runtime.h>
#include <cuda_bf16.h>
#include <math.h>
#include <stdint.h>

#define D 128
#define DIN 16
#define NMAX 100000
#define EMAX 600000

// tcgen05 is an arch-accelerated ("a") feature: only emit it in passes that
// target sm_103a / sm_100a. The plain compute_103 PTX fallback pass gets an
// empty body (never executed at runtime — the sm_103a cubin is used).
#if defined(__CUDA_ARCH_FEAT_SM103_ALL) || defined(__CUDA_ARCH_FEAT_SM100_ALL) || defined(__CUDA_ARCH_FEAT_SM101_ALL)
#define HAS_TCGEN05 1
#else
#define HAS_TCGEN05 0
#endif

// ---------------- scratch (static device globals; no allocations) ----------------
__device__ float g_h_net [(size_t)NMAX * D];
__device__ float g_h_cell[(size_t)NMAX * D];
__device__ float g_c_net [(size_t)NMAX * D];   // feat@Wla^T + bvec  (net)
__device__ float g_c_cell[(size_t)NMAX * D];   // feat@Wla^T + bvec  (cell)
__device__ float g_hsrc0 [(size_t)NMAX * D];   // h_cell@Wg0^T
__device__ float g_hsrc1 [(size_t)NMAX * D];   // h_net @Wg1^T
__device__ float g_hsrc2 [(size_t)NMAX * D];   // h_net @Wg2^T
__device__ float g_G0    [(size_t)NMAX * D];
__device__ float g_G1    [(size_t)NMAX * D];
__device__ float g_G2    [(size_t)NMAX * D];
__device__ float g_se0[EMAX], g_se1[EMAX], g_se2[EMAX];
__device__ float g_dn0[NMAX], g_dn1[NMAX], g_dn2[NMAX];
__device__ float g_el0[NMAX], g_er0[NMAX], g_el1[NMAX], g_er1[NMAX], g_el2[NMAX], g_er2[NMAX];
// vecs rows: 0 wl0(cell) 1 wr0(net) 2 wl1(net) 3 wr1(cell) 4 wl2(net) 5 wr2(net) 6 bvec
__device__ float g_vecs[7 * D];
// pre-swizzled bf16 hi/lo weight tiles: idx 0=Wla 1=Wlb 2=Wg0 3=Wg1 4=Wg2 (32768 bf16 each)
__device__ __nv_bfloat16 g_wt[5 * 32768];

// ---------------- helpers ----------------
__device__ __forceinline__ uint32_t smem_u32(const void* p) {
    uint32_t r;
    asm("{ .reg .u64 t; cvta.to.shared.u64 t, %1; cvt.u32.u64 %0, t; }" : "=r"(r) : "l"(p));
    return r;
}
__device__ __forceinline__ uint32_t elect1() {
    uint32_t p;
    asm volatile("{\n\t.reg .pred p;\n\telect.sync _|p, 0xFFFFFFFF;\n\tselp.b32 %0, 1, 0, p;\n\t}" : "=r"(p));
    return p;
}
// SW128 K-major descriptor: layout=2, version=1, SBO=64, LBO=1
__device__ __forceinline__ uint64_t mkdesc(uint32_t addr) {
    return ((uint64_t)2 << 61) | ((uint64_t)1 << 46) | ((uint64_t)64 << 32) |
           ((uint64_t)1 << 16) | ((uint64_t)(addr >> 4) & 0x3FFF);
}
// idesc kind::f16: dtype=F32, atype=btype=BF16, N=128, M=128
#define MMA_IDESC 0x08200490u

__device__ __forceinline__ void mbar_waitp(uint32_t mbar, uint32_t parity) {
    asm volatile(
        "{\n\t.reg .pred P1;\n\t"
        "WAIT_LOOP_%=:\n\t"
        "mbarrier.try_wait.parity.acquire.cta.shared::cta.b64 P1, [%0], %1, 0x989680;\n\t"
        "@P1 bra.uni WAIT_DONE_%=;\n\t"
        "bra.uni WAIT_LOOP_%=;\n\t"
        "WAIT_DONE_%=:\n\t}"
        :: "r"(mbar), "r"(parity) : "memory");
}

__device__ __forceinline__ uint32_t pk2(float a, float b) {
    uint16_t ha = __bfloat16_as_ushort(__float2bfloat16(a));
    uint16_t hb = __bfloat16_as_ushort(__float2bfloat16(b));
    return (uint32_t)ha | ((uint32_t)hb << 16);
}
__device__ __forceinline__ void split4(float4 v, uint2& hi, uint2& lo) {
    __nv_bfloat16 h0 = __float2bfloat16(v.x), h1 = __float2bfloat16(v.y);
    __nv_bfloat16 h2 = __float2bfloat16(v.z), h3 = __float2bfloat16(v.w);
    hi.x = (uint32_t)__bfloat16_as_ushort(h0) | ((uint32_t)__bfloat16_as_ushort(h1) << 16);
    hi.y = (uint32_t)__bfloat16_as_ushort(h2) | ((uint32_t)__bfloat16_as_ushort(h3) << 16);
    lo.x = pk2(v.x - __bfloat162float(h0), v.y - __bfloat162float(h1));
    lo.y = pk2(v.z - __bfloat162float(h2), v.w - __bfloat162float(h3));
}

#if HAS_TCGEN05
__device__ __forceinline__ void mma_f16_ss(uint32_t d_tmem, uint64_t a_desc, uint64_t b_desc,
                                           uint32_t en) {
    asm volatile(
        "{\n\t.reg .pred p;\n\tsetp.ne.u32 p, %4, 0;\n\t"
        "tcgen05.mma.cta_group::1.kind::f16 [%0], %1, %2, %3, {%5, %5, %5, %5}, p;\n\t}"
        :: "r"(d_tmem), "l"(a_desc), "l"(b_desc), "r"(MMA_IDESC), "r"(en), "r"(0u)
        : "memory");
}
__device__ __forceinline__ void tmem_ld_x32(uint32_t* r, uint32_t a) {
    asm volatile("tcgen05.ld.sync.aligned.32x32b.x32.b32 "
        "{%0,%1,%2,%3,%4,%5,%6,%7,%8,%9,%10,%11,%12,%13,%14,%15,"
        "%16,%17,%18,%19,%20,%21,%22,%23,%24,%25,%26,%27,%28,%29,%30,%31}, [%32];"
        : "=r"(r[0]), "=r"(r[1]), "=r"(r[2]), "=r"(r[3]), "=r"(r[4]), "=r"(r[5]),
          "=r"(r[6]), "=r"(r[7]), "=r"(r[8]), "=r"(r[9]), "=r"(r[10]), "=r"(r[11]),
          "=r"(r[12]), "=r"(r[13]), "=r"(r[14]), "=r"(r[15]), "=r"(r[16]), "=r"(r[17]),
          "=r"(r[18]), "=r"(r[19]), "=r"(r[20]), "=r"(r[21]), "=r"(r[22]), "=r"(r[23]),
          "=r"(r[24]), "=r"(r[25]), "=r"(r[26]), "=r"(r[27]), "=r"(r[28]), "=r"(r[29]),
          "=r"(r[30]), "=r"(r[31])
        : "r"(a));
}
// 3-pass split-bf16 MMA for one 128x128x128 layer: Ah*Wh + Ah*Wl + Al*Wh
__device__ __forceinline__ void issue_mma3(uint32_t sb, uint32_t aoff, uint32_t woff,
                                           uint32_t tb_d) {
    int first = 1;
#pragma unroll
    for (int pass = 0; pass < 3; pass++) {
        uint32_t a = (pass == 2) ? aoff + 32768u : aoff;
        uint32_t w = (pass == 1) ? woff + 32768u : woff;
#pragma unroll
        for (int c = 0; c < 2; c++) {
            uint64_t ad = mkdesc(sb + a + c * 16384);
            uint64_t bd = mkdesc(sb + w + c * 16384);
#pragma unroll
            for (int ks = 0; ks < 4; ks++) {
                mma_f16_ss(tb_d, ad + ks * 2, bd + ks * 2, first ? 0u : 1u);
                first = 0;
            }
        }
    }
}
// load 128xD fp32 rows (opt relu on first, opt add second), split, store swizzled hi/lo
__device__ __forceinline__ void load_split_A(const float* __restrict__ A1,
                                             const float* __restrict__ A2, int reluFirst,
                                             int row0, int nrows, char* abase, int tid) {
#pragma unroll
    for (int q0 = 0; q0 < 16; q0++) {
        int q = tid + q0 * 256;
        int row = q >> 5, k = (q & 31) << 2;
        int gr = row0 + row;
        float4 v = make_float4(0.f, 0.f, 0.f, 0.f);
        if (gr < nrows) {
            v = *(const float4*)(A1 + (size_t)gr * D + k);
            if (reluFirst) {
                v.x = fmaxf(v.x, 0.f); v.y = fmaxf(v.y, 0.f);
                v.z = fmaxf(v.z, 0.f); v.w = fmaxf(v.w, 0.f);
            }
            if (A2) {
                float4 u = *(const float4*)(A2 + (size_t)gr * D + k);
                v.x += u.x; v.y += u.y; v.z += u.z; v.w += u.w;
            }
        }
        uint2 hi, lo;
        split4(v, hi, lo);
        int chunk = k >> 6, kin = k & 63;
        uint32_t bo = row * 128 + kin * 2;
        uint32_t sw = bo ^ ((bo >> 3) & 0x70);
        *(uint2*)(abase + chunk * 16384 + sw) = hi;
        *(uint2*)(abase + chunk * 16384 + 32768 + sw) = lo;
    }
}
__device__ __forceinline__ void copy_w(const __nv_bfloat16* __restrict__ Wt, char* wbase, int tid) {
    const float4* ws = (const float4*)Wt;
    float4* wd = (float4*)wbase;
#pragma unroll
    for (int q = 0; q < 16; q++) wd[tid + q * 256] = ws[tid + q * 256];
}
// 8-warp epilogue to global: warps (w>>2) take col halves, rows = (w&3)*32+lane
__device__ __forceinline__ void ep_store_global(uint32_t tb_d, float* __restrict__ outp,
                                                int addBvec, int row0, int nrows,
                                                int wid, int lid) {
    int colb = (wid >> 2) * 64;
    int rloc = (wid & 3) * 32 + lid;
    int gr = row0 + rloc;
    uint32_t dr[64];
    tmem_ld_x32(dr, tb_d + colb);
    tmem_ld_x32(dr + 32, tb_d + colb + 32);
    asm volatile("tcgen05.wait::ld.sync.aligned;" ::: "memory");
    if (gr < nrows) {
        float4* cp = (float4*)(outp + (size_t)gr * D + colb);
#pragma unroll
        for (int j = 0; j < 16; j++) {
            float4 f = make_float4(__uint_as_float(dr[j * 4]), __uint_as_float(dr[j * 4 + 1]),
                                   __uint_as_float(dr[j * 4 + 2]), __uint_as_float(dr[j * 4 + 3]));
            if (addBvec) {
                f.x += g_vecs[6 * D + colb + j * 4];
                f.y += g_vecs[6 * D + colb + j * 4 + 1];
                f.z += g_vecs[6 * D + colb + j * 4 + 2];
                f.w += g_vecs[6 * D + colb + j * 4 + 3];
            }
            cp[j] = f;
        }
    }
    asm volatile("tcgen05.fence::before_thread_sync;" ::: "memory");
}
#endif  // HAS_TCGEN05

// ---------------- small utility kernels ----------------
__global__ void fill_all_k(int n, int nd) {
    for (int i = blockIdx.x * blockDim.x + threadIdx.x; i < nd; i += gridDim.x * blockDim.x) {
        g_G0[i] = 0.f; g_G1[i] = 0.f; g_G2[i] = 0.f;
        if (i < n) { g_dn0[i] = 0.f; g_dn1[i] = 0.f; g_dn2[i] = 0.f; }
    }
}

__global__ void proj_k(const float* __restrict__ x, const float* __restrict__ Wp,
                       float* __restrict__ h, int n) {
    int gid = blockIdx.x * blockDim.x + threadIdx.x;
    if (gid >= n * D) return;
    int row = gid >> 7, col = gid & 127;
    const float4* xr = (const float4*)(x + (size_t)row * DIN);
    const float4* wr = (const float4*)(Wp + (size_t)col * DIN);
    float s = 0.f;
#pragma unroll
    for (int i = 0; i < 4; i++) {
        float4 a = xr[i], b = wr[i];
        s += a.x * b.x + a.y * b.y + a.z * b.z + a.w * b.w;
    }
    h[gid] = s;
}

__global__ void vecprep_k(const float* Wg0, const float* al0, const float* ar0,
                          const float* Wg1, const float* al1, const float* ar1,
                          const float* Wg2, const float* al2, const float* ar2,
                          const float* Wl, const float* bias) {
    int k = threadIdx.x;
    float s;
    s = 0.f; for (int j = 0; j < D; j++) s += al0[j] * Wg0[j * D + k]; g_vecs[0 * D + k] = s;
    s = 0.f; for (int j = 0; j < D; j++) s += ar0[j] * Wg0[j * D + k]; g_vecs[1 * D + k] = s;
    s = 0.f; for (int j = 0; j < D; j++) s += al1[j] * Wg1[j * D + k]; g_vecs[2 * D + k] = s;
    s = 0.f; for (int j = 0; j < D; j++) s += ar1[j] * Wg1[j * D + k]; g_vecs[3 * D + k] = s;
    s = 0.f; for (int j = 0; j < D; j++) s += al2[j] * Wg2[j * D + k]; g_vecs[4 * D + k] = s;
    s = 0.f; for (int j = 0; j < D; j++) s += ar2[j] * Wg2[j * D + k]; g_vecs[5 * D + k] = s;
    s = 0.f; for (int j = 0; j < D; j++) s += Wl[(size_t)k * 2 * D + D + j] * bias[j]; g_vecs[6 * D + k] = s;
}

// weight prep: split fp32 into bf16 hi/lo, pre-swizzled SMEM tile images (5 weights)
__global__ void wprep_all_k(const float* __restrict__ Wl, const float* __restrict__ Wg0,
                            const float* __restrict__ Wg1, const float* __restrict__ Wg2) {
    int gid = blockIdx.x * blockDim.x + threadIdx.x;
    if (gid >= 5 * 16384) return;
    int w = gid >> 14, i = gid & 16383;
    const float* src; int ld, off;
    if (w == 0)      { src = Wl;  ld = 256; off = 0;   }
    else if (w == 1) { src = Wl;  ld = 256; off = 128; }
    else if (w == 2) { src = Wg0; ld = 128; off = 0;   }
    else if (w == 3) { src = Wg1; ld = 128; off = 0;   }
    else             { src = Wg2; ld = 128; off = 0;   }
    int j = i >> 7, k = i & 127;
    float v = src[(size_t)j * ld + off + k];
    __nv_bfloat16 h = __float2bfloat16(v);
    __nv_bfloat16 l = __float2bfloat16(v - __bfloat162float(h));
    int chunk = k >> 6;
    uint32_t bo = j * 128 + (k & 63) * 2;
    uint32_t sw = bo ^ ((bo >> 3) & 0x70);
    char* hb = (char*)g_wt + w * 65536 + chunk * 16384;
    *(__nv_bfloat16*)(hb + sw) = h;
    *(__nv_bfloat16*)(hb + 32768 + sw) = l;
}

__device__ __forceinline__ float dot4(float4 a, float4 b) {
    return a.x * b.x + a.y * b.y + a.z * b.z + a.w * b.w;
}

__global__ void node_logits_k(const float* __restrict__ hn, const float* __restrict__ hc, int n) {
    int t = blockIdx.x * blockDim.x + threadIdx.x;
    int node = t >> 5, lane = t & 31;
    if (node >= n) return;
    float4 a = ((const float4*)(hn + (size_t)node * D))[lane];
    float4 b = ((const float4*)(hc + (size_t)node * D))[lane];
    const float4* V = (const float4*)g_vecs;
    float v[6];
    v[0] = dot4(b, V[0 * 32 + lane]);
    v[1] = dot4(a, V[1 * 32 + lane]);
    v[2] = dot4(a, V[2 * 32 + lane]);
    v[3] = dot4(b, V[3 * 32 + lane]);
    v[4] = dot4(a, V[4 * 32 + lane]);
    v[5] = dot4(a, V[5 * 32 + lane]);
#pragma unroll
    for (int r = 0; r < 6; r++)
#pragma unroll
        for (int o = 16; o; o >>= 1) v[r] += __shfl_xor_sync(0xffffffffu, v[r], o);
    if (lane == 0) {
        g_el0[node] = v[0]; g_er0[node] = v[1];
        g_el1[node] = v[2]; g_er1[node] = v[3];
        g_el2[node] = v[4]; g_er2[node] = v[5];
    }
}

// fused edge softmax numerator + denominator (no max shift needed: |logit| small)
__global__ void edge12_k(const int* __restrict__ src, const int* __restrict__ dst,
                         const float* __restrict__ elv, const float* __restrict__ erv,
                         float* __restrict__ se, float* __restrict__ den, int ne) {
    int e = blockIdx.x * blockDim.x + threadIdx.x;
    if (e >= ne) return;
    float s = elv[src[e]] + erv[dst[e]];
    s = s > 0.f ? s : 0.2f * s;
    float ex = expf(s);
    se[e] = ex;
    atomicAdd(&den[dst[e]], ex);
}

// weighted scatter: G[dst] += alpha * hsrc[src]; one warp per edge, float4 atomics
__global__ void edge3_k(const int* __restrict__ src, const int* __restrict__ dst,
                        const float* __restrict__ se, const float* __restrict__ den,
                        const float* __restrict__ hsrc, float* __restrict__ G, int ne) {
    int t = blockIdx.x * blockDim.x + threadIdx.x;
    int e = t >> 5, lane = t & 31;
    if (e >= ne) return;
    int s = src[e], d = dst[e];
    float alpha = se[e] / den[d];
    float4 v = ((const float4*)(hsrc + (size_t)s * D))[lane];
    v.x *= alpha; v.y *= alpha; v.z *= alpha; v.w *= alpha;
    atomicAdd(((float4*)(G + (size_t)d * D)) + lane, v);
}

// ---------------- fused 5-GEMM kernel (c_net, hs1, hs2, c_cell, hs0) ----------------
// smem: [0] tmem ptr, [8],[16] mbarriers, A_net hi/lo 64KB, A_cell hi/lo 64KB, W 64KB
#define SM_A0 1024
#define SM_A1 (1024 + 65536)
#define SM_W5 (1024 + 131072)
#define SM5_TOTAL (1024 + 196608)

__global__ __launch_bounds__(256, 1) void gemm5_k(int nrows) {
#if HAS_TCGEN05
    extern __shared__ char smem[];
    uint32_t sb = smem_u32(smem);
    int tid = threadIdx.x, wid = tid >> 5, lid = tid & 31;
    int row0 = blockIdx.x * 128;

    if (tid == 0) {
        asm volatile("mbarrier.init.shared.b64 [%0], 1;" :: "r"(sb + 8) : "memory");
        asm volatile("mbarrier.init.shared.b64 [%0], 1;" :: "r"(sb + 16) : "memory");
    }
    if (wid == 0)
        asm volatile("tcgen05.alloc.cta_group::1.sync.aligned.shared::cta.b32 [%0], %1;"
                     :: "r"(sb), "r"(512u) : "memory");
    __syncthreads();
    uint32_t tb = *(volatile uint32_t*)smem;

    load_split_A(g_h_net,  nullptr, 0, row0, nrows, smem + SM_A0, tid);
    load_split_A(g_h_cell, nullptr, 0, row0, nrows, smem + SM_A1, tid);
    copy_w(g_wt + 0 * 32768, smem + SM_W5, tid);   // W for layer 0 (Wla)
    asm volatile("fence.proxy.async.shared::cta;" ::: "memory");
    __syncthreads();

    const uint32_t aoff[5] = {SM_A0, SM_A0, SM_A0, SM_A1, SM_A1};
    const int wsel[5] = {0, 3, 4, 0, 2};
    float* const outp[5] = {g_c_net, g_hsrc1, g_hsrc2, g_c_cell, g_hsrc0};
    const int bvf[5] = {1, 0, 0, 1, 0};
    const uint32_t par[5] = {0, 0, 1, 1, 0};

#pragma unroll
    for (int i = 0; i < 5; i++) {
        asm volatile("tcgen05.fence::after_thread_sync;" ::: "memory");
        if (wid == 0 && elect1()) {
            issue_mma3(sb, aoff[i], SM_W5, tb + (i & 1) * 128);
            asm volatile(
                "tcgen05.commit.cta_group::1.mbarrier::arrive::one.shared::cluster.b64 [%0];"
                :: "r"(sb + 8 + (i & 1) * 8) : "memory");
        }
        if (i > 0)   // epilogue of previous layer overlaps this layer's MMA
            ep_store_global(tb + ((i - 1) & 1) * 128, outp[i - 1], bvf[i - 1],
                            row0, nrows, wid, lid);
        mbar_waitp(sb + 8 + (i & 1) * 8, par[i]);   // MMA_i done (W safe to overwrite)
        if (i < 4) {
            copy_w(g_wt + wsel[i + 1] * 32768, smem + SM_W5, tid);
            asm volatile("fence.proxy.async.shared::cta;" ::: "memory");
            __syncthreads();
        }
    }
    asm volatile("tcgen05.fence::after_thread_sync;" ::: "memory");
    ep_store_global(tb + 0, outp[4], bvf[4], row0, nrows, wid, lid);

    __syncthreads();
    if (wid == 0) {
        asm volatile("tcgen05.relinquish_alloc_permit.cta_group::1.sync.aligned;");
        asm volatile("tcgen05.dealloc.cta_group::1.sync.aligned.b32 %0, %1;" :: "r"(tb), "r"(512u));
    }
#endif
}

// ---------------- fused F-chain kernel ----------------
// net CTAs (blockIdx < gbn):  out_net = relu(C+ (relu(C+ relu(C+G0@W)@W) + G2)@W)
// cell CTAs: out_cell = relu(C + relu(C + (relu(C)+G1)@W)@W)      (C includes bvec)
// smem: A hi/lo 64KB, W (Wlb) 64KB, C fp32 tile padded stride 129 (66048 B)
#define SMC_A 1024
#define SMC_W (1024 + 65536)
#define SMC_C (1024 + 131072)
#define SMC_TOTAL (1024 + 131072 + 66048)

__global__ __launch_bounds__(256, 1) void chain_k(float* __restrict__ out, int nrows, int gbn) {
#if HAS_TCGEN05
    extern __shared__ char smem[];
    uint32_t sb = smem_u32(smem);
    int tid = threadIdx.x, wid = tid >> 5, lid = tid & 31;
    int isNet = blockIdx.x < gbn;
    int row0 = (isNet ? blockIdx.x : blockIdx.x - gbn) * 128;

    if (tid == 0)
        asm volatile("mbarrier.init.shared.b64 [%0], 1;" :: "r"(sb + 8) : "memory");
    if (wid == 0)
        asm volatile("tcgen05.alloc.cta_group::1.sync.aligned.shared::cta.b32 [%0], %1;"
                     :: "r"(sb), "r"(512u) : "memory");
    __syncthreads();
    uint32_t tb = *(volatile uint32_t*)smem;

    const float* Cg = isNet ? g_c_net : g_c_cell;
    float* Cs = (float*)(smem + SMC_C);
    // C tile into smem, padded stride 129 floats (conflict-free scalar reads)
#pragma unroll
    for (int q0 = 0; q0 < 16; q0++) {
        int q = tid + q0 * 256;
        int row = q >> 5, k = (q & 31) << 2;
        int gr = row0 + row;
        float4 v = make_float4(0.f, 0.f, 0.f, 0.f);
        if (gr < nrows) v = *(const float4*)(Cg + (size_t)gr * D + k);
        Cs[row * 129 + k] = v.x; Cs[row * 129 + k + 1] = v.y;
        Cs[row * 129 + k + 2] = v.z; Cs[row * 129 + k + 3] = v.w;
    }
    // first A:  net -> G0 ; cell -> relu(C)+G1
    if (isNet) load_split_A(g_G0, nullptr, 0, row0, nrows, smem + SMC_A, tid);
    else       load_split_A(g_c_cell, g_G1, 1, row0, nrows, smem + SMC_A, tid);
    copy_w(g_wt + 1 * 32768, smem + SMC_W, tid);   // Wlb
    asm volatile("fence.proxy.async.shared::cta;" ::: "memory");
    __syncthreads();

    int nl = isNet ? 3 : 2;
    int colb = (wid >> 2) * 64;
    int rloc = (wid & 3) * 32 + lid;
    int gr = row0 + rloc;

    for (int l = 0; l < nl; l++) {
        asm volatile("tcgen05.fence::after_thread_sync;" ::: "memory");
        if (wid == 0 && elect1()) {
            issue_mma3(sb, SMC_A, SMC_W, tb);
            asm volatile(
                "tcgen05.commit.cta_group::1.mbarrier::arrive::one.shared::cluster.b64 [%0];"
                :: "r"(sb + 8) : "memory");
        }
        mbar_waitp(sb + 8, (uint32_t)(l & 1));
        asm volatile("tcgen05.fence::after_thread_sync;" ::: "memory");

        uint32_t dr[64];
        tmem_ld_x32(dr, tb + colb);
        tmem_ld_x32(dr + 32, tb + colb + 32);
        asm volatile("tcgen05.wait::ld.sync.aligned;" ::: "memory");

        float o[64];
#pragma unroll
        for (int j = 0; j < 64; j++) {
            float v = __uint_as_float(dr[j]) + Cs[rloc * 129 + colb + j];
            o[j] = v > 0.f ? v : 0.f;
        }
        if (l == nl - 1) {
            if (gr < nrows) {
                float4* dp = (float4*)(out + (size_t)(isNet ? gr : nrows + gr) * D + colb);
#pragma unroll
                for (int j = 0; j < 16; j++)
                    dp[j] = make_float4(o[j * 4], o[j * 4 + 1], o[j * 4 + 2], o[j * 4 + 3]);
            }
            asm volatile("tcgen05.fence::before_thread_sync;" ::: "memory");
        } else {
            if (isNet && l == 1 && gr < nrows) {   // add G2 before final layer
                const float4* g2 = (const float4*)(g_G2 + (size_t)gr * D + colb);
#pragma unroll
                for (int j = 0; j < 16; j++) {
                    float4 u = g2[j];
                    o[j * 4] += u.x; o[j * 4 + 1] += u.y; o[j * 4 + 2] += u.z; o[j * 4 + 3] += u.w;
                }
            }
            // re-split into A smem (rows beyond nrows are exact zeros: acc=0, C=0)
#pragma unroll
            for (int j = 0; j < 16; j++) {
                float4 v = make_float4(o[j * 4], o[j * 4 + 1], o[j * 4 + 2], o[j * 4 + 3]);
                uint2 hi, lo;
                split4(v, hi, lo);
                int chunk = colb >> 6;
                uint32_t bo = rloc * 128 + (j * 4) * 2;
                uint32_t sw = bo ^ ((bo >> 3) & 0x70);
                *(uint2*)(smem + SMC_A + chunk * 16384 + sw) = hi;
                *(uint2*)(smem + SMC_A + chunk * 16384 + 32768 + sw) = lo;
            }
            asm volatile("fence.proxy.async.shared::cta;" ::: "memory");
            asm volatile("tcgen05.fence::before_thread_sync;" ::: "memory");
            __syncthreads();
        }
    }

    __syncthreads();
    if (wid == 0) {
        asm volatile("tcgen05.relinquish_alloc_permit.cta_group::1.sync.aligned;");
        asm volatile("tcgen05.dealloc.cta_group::1.sync.aligned.b32 %0, %1;" :: "r"(tb), "r"(512u));
    }
#endif
}

// ---------------- host launch ----------------
extern "C" void kernel_launch(void* const* d_in, const int* in_sizes, int n_in,
                              void* d_out, int out_size) {
    const float* x_net   = (const float*)d_in[0];
    const float* x_cell  = (const float*)d_in[1];
    const float* Wp_net  = (const float*)d_in[2];
    const float* Wp_cell = (const float*)d_in[3];
    const float* Wg0 = (const float*)d_in[4];
    const float* al0 = (const float*)d_in[5];
    const float* ar0 = (const float*)d_in[6];
    const float* Wg1 = (const float*)d_in[7];
    const float* al1 = (const float*)d_in[8];
    const float* ar1 = (const float*)d_in[9];
    const float* Wg2 = (const float*)d_in[10];
    const float* al2 = (const float*)d_in[11];
    const float* ar2 = (const float*)d_in[12];
    const float* Wl   = (const float*)d_in[13];
    const float* bias = (const float*)d_in[14];
    const int* src0 = (const int*)d_in[15];
    const int* dst0 = (const int*)d_in[16];
    const int* src1 = (const int*)d_in[17];
    const int* dst1 = (const int*)d_in[18];
    const int* src2 = (const int*)d_in[19];
    const int* dst2 = (const int*)d_in[20];

    int n  = in_sizes[0] / DIN;
    int E0 = in_sizes[15], E1 = in_sizes[17], E2 = in_sizes[19];
    float* out = (float*)d_out;
    int nd = n * D, gb = (n + 127) / 128;

    float *h_net, *h_cell, *hs0, *hs1, *hs2, *G0, *G1, *G2;
    float *se0, *se1, *se2, *dn0, *dn1, *dn2;
    float *el0, *er0, *el1, *er1, *el2, *er2;
    cudaGetSymbolAddress((void**)&h_net, g_h_net);
    cudaGetSymbolAddress((void**)&h_cell, g_h_cell);
    cudaGetSymbolAddress((void**)&hs0, g_hsrc0);
    cudaGetSymbolAddress((void**)&hs1, g_hsrc1);
    cudaGetSymbolAddress((void**)&hs2, g_hsrc2);
    cudaGetSymbolAddress((void**)&G0, g_G0);
    cudaGetSymbolAddress((void**)&G1, g_G1);
    cudaGetSymbolAddress((void**)&G2, g_G2);
    cudaGetSymbolAddress((void**)&se0, g_se0);
    cudaGetSymbolAddress((void**)&se1, g_se1);
    cudaGetSymbolAddress((void**)&se2, g_se2);
    cudaGetSymbolAddress((void**)&dn0, g_dn0);
    cudaGetSymbolAddress((void**)&dn1, g_dn1);
    cudaGetSymbolAddress((void**)&dn2, g_dn2);
    cudaGetSymbolAddress((void**)&el0, g_el0);
    cudaGetSymbolAddress((void**)&er0, g_er0);
    cudaGetSymbolAddress((void**)&el1, g_el1);
    cudaGetSymbolAddress((void**)&er1, g_er1);
    cudaGetSymbolAddress((void**)&el2, g_el2);
    cudaGetSymbolAddress((void**)&er2, g_er2);

    cudaFuncSetAttribute(gemm5_k, cudaFuncAttributeMaxDynamicSharedMemorySize, SM5_TOTAL);
    cudaFuncSetAttribute(chain_k, cudaFuncAttributeMaxDynamicSharedMemorySize, SMC_TOTAL);

    // launch order chosen so launch #6 (ncu -s 5 -c 1) is gemm5_k
    vecprep_k<<<1, 128>>>(Wg0, al0, ar0, Wg1, al1, ar1, Wg2, al2, ar2, Wl, bias);   // 1
    wprep_all_k<<<(5 * 16384 + 255) / 256, 256>>>(Wl, Wg0, Wg1, Wg2);               // 2
    fill_all_k<<<1024, 256>>>(n, nd);                                               // 3
    proj_k<<<(nd + 255) / 256, 256>>>(x_net, Wp_net, h_net, n);                     // 4
    proj_k<<<(nd + 255) / 256, 256>>>(x_cell, Wp_cell, h_cell, n);                  // 5
    gemm5_k<<<gb, 256, SM5_TOTAL>>>(n);                                             // 6 <- profiled
    node_logits_k<<<(n * 32 + 255) / 256, 256>>>(h_net, h_cell, n);                 // 7
    edge12_k<<<(E0 + 255) / 256, 256>>>(src0, dst0, el0, er0, se0, dn0, E0);        // 8
    edge12_k<<<(E1 + 255) / 256, 256>>>(src1, dst1, el1, er1, se1, dn1, E1);        // 9
    edge12_k<<<(E2 + 255) / 256, 256>>>(src2, dst2, el2, er2, se2, dn2, E2);        // 10
    edge3_k<<<(E0 * 32 + 255) / 256, 256>>>(src0, dst0, se0, dn0, hs0, G0, E0);     // 11
    edge3_k<<<(E1 * 32 + 255) / 256, 256>>>(src1, dst1, se1, dn1, hs1, G1, E1);     // 12
    edge3_k<<<(E2 * 32 + 255) / 256, 256>>>(src2, dst2, se2, dn2, hs2, G2, E2);     // 13
    chain_k<<<2 * gb, 256, SMC_TOTAL>>>(out, n, gb);                                // 14
}

// round 14
// speedup vs baseline: 1.1427x; 1.1427x over previous
#include <cuda_runtime.h>
#include <cuda_bf16.h>
#include <math.h>
#include <stdint.h>

#define D 128
#define DIN 16
#define NMAX 100000
#define EMAX 600000

// tcgen05 is an arch-accelerated ("a") feature: only emit it in passes that
// target sm_103a / sm_100a. The plain compute_103 PTX fallback pass gets an
// empty body (never executed at runtime — the sm_103a cubin is used).
#if defined(__CUDA_ARCH_FEAT_SM103_ALL) || defined(__CUDA_ARCH_FEAT_SM100_ALL) || defined(__CUDA_ARCH_FEAT_SM101_ALL)
#define HAS_TCGEN05 1
#else
#define HAS_TCGEN05 0
#endif

// ---------------- scratch (static device globals; no allocations) ----------------
__device__ float g_h_net [(size_t)NMAX * D];
__device__ float g_h_cell[(size_t)NMAX * D];
__device__ float g_c_net [(size_t)NMAX * D];   // feat@Wla^T + bvec  (net)
__device__ float g_c_cell[(size_t)NMAX * D];   // feat@Wla^T + bvec  (cell)
__device__ float g_hsrc0 [(size_t)NMAX * D];   // h_cell@Wg0^T
__device__ float g_hsrc1 [(size_t)NMAX * D];   // h_net @Wg1^T
__device__ float g_hsrc2 [(size_t)NMAX * D];   // h_net @Wg2^T
__device__ float g_G0    [(size_t)NMAX * D];
__device__ float g_G1    [(size_t)NMAX * D];
__device__ float g_G2    [(size_t)NMAX * D];
__device__ float g_se0[EMAX], g_se1[EMAX], g_se2[EMAX];
__device__ float g_dn0[NMAX], g_dn1[NMAX], g_dn2[NMAX];
__device__ float g_el0[NMAX], g_er0[NMAX], g_el1[NMAX], g_er1[NMAX], g_el2[NMAX], g_er2[NMAX];
// vecs rows: 0 wl0(cell) 1 wr0(net) 2 wl1(net) 3 wr1(cell) 4 wl2(net) 5 wr2(net) 6 bvec
__device__ float g_vecs[7 * D];
// pre-swizzled bf16 hi/lo weight tiles: idx 0=Wla 1=Wlb 2=Wg0 3=Wg1 4=Wg2 (32768 bf16 each)
__device__ __nv_bfloat16 g_wt[5 * 32768];

// ---------------- helpers ----------------
__device__ __forceinline__ uint32_t smem_u32(const void* p) {
    uint32_t r;
    asm("{ .reg .u64 t; cvta.to.shared.u64 t, %1; cvt.u32.u64 %0, t; }" : "=r"(r) : "l"(p));
    return r;
}
__device__ __forceinline__ uint32_t elect1() {
    uint32_t p;
    asm volatile("{\n\t.reg .pred p;\n\telect.sync _|p, 0xFFFFFFFF;\n\tselp.b32 %0, 1, 0, p;\n\t}" : "=r"(p));
    return p;
}
// SW128 K-major descriptor: layout=2, version=1, SBO=64, LBO=1
__device__ __forceinline__ uint64_t mkdesc(uint32_t addr) {
    return ((uint64_t)2 << 61) | ((uint64_t)1 << 46) | ((uint64_t)64 << 32) |
           ((uint64_t)1 << 16) | ((uint64_t)(addr >> 4) & 0x3FFF);
}
// idesc kind::f16: dtype=F32, atype=btype=BF16, N=128, M=128
#define MMA_IDESC 0x08200490u

__device__ __forceinline__ void mbar_waitp(uint32_t mbar, uint32_t parity) {
    asm volatile(
        "{\n\t.reg .pred P1;\n\t"
        "WAIT_LOOP_%=:\n\t"
        "mbarrier.try_wait.parity.acquire.cta.shared::cta.b64 P1, [%0], %1, 0x989680;\n\t"
        "@P1 bra.uni WAIT_DONE_%=;\n\t"
        "bra.uni WAIT_LOOP_%=;\n\t"
        "WAIT_DONE_%=:\n\t}"
        :: "r"(mbar), "r"(parity) : "memory");
}

__device__ __forceinline__ uint32_t pk2(float a, float b) {
    uint16_t ha = __bfloat16_as_ushort(__float2bfloat16(a));
    uint16_t hb = __bfloat16_as_ushort(__float2bfloat16(b));
    return (uint32_t)ha | ((uint32_t)hb << 16);
}
__device__ __forceinline__ void split4(float4 v, uint2& hi, uint2& lo) {
    __nv_bfloat16 h0 = __float2bfloat16(v.x), h1 = __float2bfloat16(v.y);
    __nv_bfloat16 h2 = __float2bfloat16(v.z), h3 = __float2bfloat16(v.w);
    hi.x = (uint32_t)__bfloat16_as_ushort(h0) | ((uint32_t)__bfloat16_as_ushort(h1) << 16);
    hi.y = (uint32_t)__bfloat16_as_ushort(h2) | ((uint32_t)__bfloat16_as_ushort(h3) << 16);
    lo.x = pk2(v.x - __bfloat162float(h0), v.y - __bfloat162float(h1));
    lo.y = pk2(v.z - __bfloat162float(h2), v.w - __bfloat162float(h3));
}

#if HAS_TCGEN05
__device__ __forceinline__ void mma_f16_ss(uint32_t d_tmem, uint64_t a_desc, uint64_t b_desc,
                                           uint32_t en) {
    asm volatile(
        "{\n\t.reg .pred p;\n\tsetp.ne.u32 p, %4, 0;\n\t"
        "tcgen05.mma.cta_group::1.kind::f16 [%0], %1, %2, %3, {%5, %5, %5, %5}, p;\n\t}"
        :: "r"(d_tmem), "l"(a_desc), "l"(b_desc), "r"(MMA_IDESC), "r"(en), "r"(0u)
        : "memory");
}
__device__ __forceinline__ void tmem_ld_x32(uint32_t* r, uint32_t a) {
    asm volatile("tcgen05.ld.sync.aligned.32x32b.x32.b32 "
        "{%0,%1,%2,%3,%4,%5,%6,%7,%8,%9,%10,%11,%12,%13,%14,%15,"
        "%16,%17,%18,%19,%20,%21,%22,%23,%24,%25,%26,%27,%28,%29,%30,%31}, [%32];"
        : "=r"(r[0]), "=r"(r[1]), "=r"(r[2]), "=r"(r[3]), "=r"(r[4]), "=r"(r[5]),
          "=r"(r[6]), "=r"(r[7]), "=r"(r[8]), "=r"(r[9]), "=r"(r[10]), "=r"(r[11]),
          "=r"(r[12]), "=r"(r[13]), "=r"(r[14]), "=r"(r[15]), "=r"(r[16]), "=r"(r[17]),
          "=r"(r[18]), "=r"(r[19]), "=r"(r[20]), "=r"(r[21]), "=r"(r[22]), "=r"(r[23]),
          "=r"(r[24]), "=r"(r[25]), "=r"(r[26]), "=r"(r[27]), "=r"(r[28]), "=r"(r[29]),
          "=r"(r[30]), "=r"(r[31])
        : "r"(a));
}
// 3-pass split-bf16 MMA for one 128x128x128 layer: Ah*Wh + Ah*Wl + Al*Wh
__device__ __forceinline__ void issue_mma3(uint32_t sb, uint32_t aoff, uint32_t woff,
                                           uint32_t tb_d) {
    int first = 1;
#pragma unroll
    for (int pass = 0; pass < 3; pass++) {
        uint32_t a = (pass == 2) ? aoff + 32768u : aoff;
        uint32_t w = (pass == 1) ? woff + 32768u : woff;
#pragma unroll
        for (int c = 0; c < 2; c++) {
            uint64_t ad = mkdesc(sb + a + c * 16384);
            uint64_t bd = mkdesc(sb + w + c * 16384);
#pragma unroll
            for (int ks = 0; ks < 4; ks++) {
                mma_f16_ss(tb_d, ad + ks * 2, bd + ks * 2, first ? 0u : 1u);
                first = 0;
            }
        }
    }
}
// load 128xD fp32 rows (opt relu on first, opt add second), split, store swizzled hi/lo
__device__ __forceinline__ void load_split_A(const float* __restrict__ A1,
                                             const float* __restrict__ A2, int reluFirst,
                                             int row0, int nrows, char* abase, int tid) {
#pragma unroll
    for (int q0 = 0; q0 < 16; q0++) {
        int q = tid + q0 * 256;
        int row = q >> 5, k = (q & 31) << 2;
        int gr = row0 + row;
        float4 v = make_float4(0.f, 0.f, 0.f, 0.f);
        if (gr < nrows) {
            v = *(const float4*)(A1 + (size_t)gr * D + k);
            if (reluFirst) {
                v.x = fmaxf(v.x, 0.f); v.y = fmaxf(v.y, 0.f);
                v.z = fmaxf(v.z, 0.f); v.w = fmaxf(v.w, 0.f);
            }
            if (A2) {
                float4 u = *(const float4*)(A2 + (size_t)gr * D + k);
                v.x += u.x; v.y += u.y; v.z += u.z; v.w += u.w;
            }
        }
        uint2 hi, lo;
        split4(v, hi, lo);
        int chunk = k >> 6, kin = k & 63;
        uint32_t bo = row * 128 + kin * 2;
        uint32_t sw = bo ^ ((bo >> 3) & 0x70);
        *(uint2*)(abase + chunk * 16384 + sw) = hi;
        *(uint2*)(abase + chunk * 16384 + 32768 + sw) = lo;
    }
}
__device__ __forceinline__ void copy_w(const __nv_bfloat16* __restrict__ Wt, char* wbase, int tid) {
    const float4* ws = (const float4*)Wt;
    float4* wd = (float4*)wbase;
#pragma unroll
    for (int q = 0; q < 16; q++) wd[tid + q * 256] = ws[tid + q * 256];
}
// 8-warp epilogue to global: warps (w>>2) take col halves, rows = (w&3)*32+lane
__device__ __forceinline__ void ep_store_global(uint32_t tb_d, float* __restrict__ outp,
                                                int addBvec, int row0, int nrows,
                                                int wid, int lid) {
    int colb = (wid >> 2) * 64;
    int rloc = (wid & 3) * 32 + lid;
    int gr = row0 + rloc;
    uint32_t dr[64];
    tmem_ld_x32(dr, tb_d + colb);
    tmem_ld_x32(dr + 32, tb_d + colb + 32);
    asm volatile("tcgen05.wait::ld.sync.aligned;" ::: "memory");
    if (gr < nrows) {
        float4* cp = (float4*)(outp + (size_t)gr * D + colb);
#pragma unroll
        for (int j = 0; j < 16; j++) {
            float4 f = make_float4(__uint_as_float(dr[j * 4]), __uint_as_float(dr[j * 4 + 1]),
                                   __uint_as_float(dr[j * 4 + 2]), __uint_as_float(dr[j * 4 + 3]));
            if (addBvec) {
                f.x += g_vecs[6 * D + colb + j * 4];
                f.y += g_vecs[6 * D + colb + j * 4 + 1];
                f.z += g_vecs[6 * D + colb + j * 4 + 2];
                f.w += g_vecs[6 * D + colb + j * 4 + 3];
            }
            cp[j] = f;
        }
    }
    asm volatile("tcgen05.fence::before_thread_sync;" ::: "memory");
}
#endif  // HAS_TCGEN05

// ---------------- small utility kernels ----------------
__global__ void fill_all_k(int n, int nd4) {
    float4 z = make_float4(0.f, 0.f, 0.f, 0.f);
    for (int i = blockIdx.x * blockDim.x + threadIdx.x; i < nd4; i += gridDim.x * blockDim.x) {
        ((float4*)g_G0)[i] = z; ((float4*)g_G1)[i] = z; ((float4*)g_G2)[i] = z;
        if (i < n) { g_dn0[i] = 0.f; g_dn1[i] = 0.f; g_dn2[i] = 0.f; }
    }
}

__global__ void vecprep_k(const float* Wg0, const float* al0, const float* ar0,
                          const float* Wg1, const float* al1, const float* ar1,
                          const float* Wg2, const float* al2, const float* ar2,
                          const float* Wl, const float* bias) {
    int k = threadIdx.x;
    float s;
    s = 0.f; for (int j = 0; j < D; j++) s += al0[j] * Wg0[j * D + k]; g_vecs[0 * D + k] = s;
    s = 0.f; for (int j = 0; j < D; j++) s += ar0[j] * Wg0[j * D + k]; g_vecs[1 * D + k] = s;
    s = 0.f; for (int j = 0; j < D; j++) s += al1[j] * Wg1[j * D + k]; g_vecs[2 * D + k] = s;
    s = 0.f; for (int j = 0; j < D; j++) s += ar1[j] * Wg1[j * D + k]; g_vecs[3 * D + k] = s;
    s = 0.f; for (int j = 0; j < D; j++) s += al2[j] * Wg2[j * D + k]; g_vecs[4 * D + k] = s;
    s = 0.f; for (int j = 0; j < D; j++) s += ar2[j] * Wg2[j * D + k]; g_vecs[5 * D + k] = s;
    s = 0.f; for (int j = 0; j < D; j++) s += Wl[(size_t)k * 2 * D + D + j] * bias[j]; g_vecs[6 * D + k] = s;
}

// weight prep: split fp32 into bf16 hi/lo, pre-swizzled SMEM tile images (5 weights)
__global__ void wprep_all_k(const float* __restrict__ Wl, const float* __restrict__ Wg0,
                            const float* __restrict__ Wg1, const float* __restrict__ Wg2) {
    int gid = blockIdx.x * blockDim.x + threadIdx.x;
    if (gid >= 5 * 16384) return;
    int w = gid >> 14, i = gid & 16383;
    const float* src; int ld, off;
    if (w == 0)      { src = Wl;  ld = 256; off = 0;   }
    else if (w == 1) { src = Wl;  ld = 256; off = 128; }
    else if (w == 2) { src = Wg0; ld = 128; off = 0;   }
    else if (w == 3) { src = Wg1; ld = 128; off = 0;   }
    else             { src = Wg2; ld = 128; off = 0;   }
    int j = i >> 7, k = i & 127;
    float v = src[(size_t)j * ld + off + k];
    __nv_bfloat16 h = __float2bfloat16(v);
    __nv_bfloat16 l = __float2bfloat16(v - __bfloat162float(h));
    int chunk = k >> 6;
    uint32_t bo = j * 128 + (k & 63) * 2;
    uint32_t sw = bo ^ ((bo >> 3) & 0x70);
    char* hb = (char*)g_wt + w * 65536 + chunk * 16384;
    *(__nv_bfloat16*)(hb + sw) = h;
    *(__nv_bfloat16*)(hb + 32768 + sw) = l;
}

// ---------------- fused projection + attention logits: one warp per node ----------------
// h[node] = x[node] @ Wp^T (K=16), written coalesced; logit dots computed in-warp.
__global__ __launch_bounds__(256) void projlog_k(
    const float* __restrict__ xn, const float* __restrict__ xc,
    const float* __restrict__ Wpn, const float* __restrict__ Wpc, int n) {
    __shared__ float Ws[2][128 * 17];   // padded stride 17 -> conflict-free
    __shared__ float vs[6 * D];
    int tid = threadIdx.x;
    for (int i = tid; i < 2048; i += 256) {
        int d = i >> 4, k = i & 15;
        Ws[0][d * 17 + k] = Wpn[i];
        Ws[1][d * 17 + k] = Wpc[i];
    }
    for (int i = tid; i < 6 * D; i += 256) vs[i] = g_vecs[i];
    __syncthreads();

    int gw = blockIdx.x * 8 + (tid >> 5);
    if (gw >= 2 * n) return;
    int lane = tid & 31;
    int type = gw >= n ? 1 : 0;
    int node = gw - type * n;

    const float4* x4 = (const float4*)((type ? xc : xn) + (size_t)node * DIN);
    float xf[16];
#pragma unroll
    for (int i = 0; i < 4; i++) {
        float4 v = x4[i];
        xf[i * 4] = v.x; xf[i * 4 + 1] = v.y; xf[i * 4 + 2] = v.z; xf[i * 4 + 3] = v.w;
    }
    const float* W = Ws[type];
    float h[4];
#pragma unroll
    for (int j = 0; j < 4; j++) {
        const float* wc = W + (lane + 32 * j) * 17;
        float acc = 0.f;
#pragma unroll
        for (int k = 0; k < 16; k++) acc = fmaf(xf[k], wc[k], acc);
        h[j] = acc;
    }
    float* hp = (type ? g_h_cell : g_h_net) + (size_t)node * D + lane;
#pragma unroll
    for (int j = 0; j < 4; j++) hp[32 * j] = h[j];

    if (type == 0) {   // net: er0(vec1) el1(vec2) el2(vec4) er2(vec5)
        float s1 = 0.f, s2 = 0.f, s4 = 0.f, s5 = 0.f;
#pragma unroll
        for (int j = 0; j < 4; j++) {
            int c = lane + 32 * j;
            s1 += h[j] * vs[1 * D + c]; s2 += h[j] * vs[2 * D + c];
            s4 += h[j] * vs[4 * D + c]; s5 += h[j] * vs[5 * D + c];
        }
#pragma unroll
        for (int o = 16; o; o >>= 1) {
            s1 += __shfl_xor_sync(0xffffffffu, s1, o);
            s2 += __shfl_xor_sync(0xffffffffu, s2, o);
            s4 += __shfl_xor_sync(0xffffffffu, s4, o);
            s5 += __shfl_xor_sync(0xffffffffu, s5, o);
        }
        if (lane == 0) { g_er0[node] = s1; g_el1[node] = s2; g_el2[node] = s4; g_er2[node] = s5; }
    } else {           // cell: el0(vec0) er1(vec3)
        float s0 = 0.f, s3 = 0.f;
#pragma unroll
        for (int j = 0; j < 4; j++) {
            int c = lane + 32 * j;
            s0 += h[j] * vs[0 * D + c]; s3 += h[j] * vs[3 * D + c];
        }
#pragma unroll
        for (int o = 16; o; o >>= 1) {
            s0 += __shfl_xor_sync(0xffffffffu, s0, o);
            s3 += __shfl_xor_sync(0xffffffffu, s3, o);
        }
        if (lane == 0) { g_el0[node] = s0; g_er1[node] = s3; }
    }
}

// fused edge softmax numerator + denominator, all 3 relations in one launch
__global__ void edge12m_k(const int* __restrict__ src0, const int* __restrict__ dst0,
                          const int* __restrict__ src1, const int* __restrict__ dst1,
                          const int* __restrict__ src2, const int* __restrict__ dst2,
                          int E0, int E1, int E2) {
    int e = blockIdx.x * blockDim.x + threadIdx.x;
    const int *src, *dst; const float *elv, *erv; float *se, *den;
    if (e < E0) {
        src = src0; dst = dst0; elv = g_el0; erv = g_er0; se = g_se0; den = g_dn0;
    } else if (e < E0 + E1) {
        e -= E0;
        src = src1; dst = dst1; elv = g_el1; erv = g_er1; se = g_se1; den = g_dn1;
    } else if (e < E0 + E1 + E2) {
        e -= E0 + E1;
        src = src2; dst = dst2; elv = g_el2; erv = g_er2; se = g_se2; den = g_dn2;
    } else return;
    float s = elv[src[e]] + erv[dst[e]];
    s = s > 0.f ? s : 0.2f * s;
    float ex = expf(s);
    se[e] = ex;
    atomicAdd(&den[dst[e]], ex);
}

// weighted scatter for all 3 relations: G[dst] += alpha * hsrc[src]; warp/edge, float4 atomics
__global__ void edge3m_k(const int* __restrict__ src0, const int* __restrict__ dst0,
                         const int* __restrict__ src1, const int* __restrict__ dst1,
                         const int* __restrict__ src2, const int* __restrict__ dst2,
                         int E0, int E1, int E2) {
    int t = blockIdx.x * blockDim.x + threadIdx.x;
    int e = t >> 5, lane = t & 31;
    const int *src, *dst; const float *se, *den, *hs; float *G;
    if (e < E0) {
        src = src0; dst = dst0; se = g_se0; den = g_dn0; hs = g_hsrc0; G = g_G0;
    } else if (e < E0 + E1) {
        e -= E0;
        src = src1; dst = dst1; se = g_se1; den = g_dn1; hs = g_hsrc1; G = g_G1;
    } else if (e < E0 + E1 + E2) {
        e -= E0 + E1;
        src = src2; dst = dst2; se = g_se2; den = g_dn2; hs = g_hsrc2; G = g_G2;
    } else return;
    int s = src[e], d = dst[e];
    float alpha = se[e] / den[d];
    float4 v = ((const float4*)(hs + (size_t)s * D))[lane];
    v.x *= alpha; v.y *= alpha; v.z *= alpha; v.w *= alpha;
    atomicAdd(((float4*)(G + (size_t)d * D)) + lane, v);
}

// ---------------- fused 5-GEMM kernel (c_net, hs1, hs2, c_cell, hs0) ----------------
// smem: [0] tmem ptr, [8],[16] mbarriers, A_net hi/lo 64KB, A_cell hi/lo 64KB, W 64KB
#define SM_A0 1024
#define SM_A1 (1024 + 65536)
#define SM_W5 (1024 + 131072)
#define SM5_TOTAL (1024 + 196608)

__global__ __launch_bounds__(256, 1) void gemm5_k(int nrows) {
#if HAS_TCGEN05
    extern __shared__ char smem[];
    uint32_t sb = smem_u32(smem);
    int tid = threadIdx.x, wid = tid >> 5, lid = tid & 31;
    int row0 = blockIdx.x * 128;

    if (tid == 0) {
        asm volatile("mbarrier.init.shared.b64 [%0], 1;" :: "r"(sb + 8) : "memory");
        asm volatile("mbarrier.init.shared.b64 [%0], 1;" :: "r"(sb + 16) : "memory");
    }
    if (wid == 0)
        asm volatile("tcgen05.alloc.cta_group::1.sync.aligned.shared::cta.b32 [%0], %1;"
                     :: "r"(sb), "r"(512u) : "memory");
    __syncthreads();
    uint32_t tb = *(volatile uint32_t*)smem;

    load_split_A(g_h_net,  nullptr, 0, row0, nrows, smem + SM_A0, tid);
    load_split_A(g_h_cell, nullptr, 0, row0, nrows, smem + SM_A1, tid);
    copy_w(g_wt + 0 * 32768, smem + SM_W5, tid);   // W for layer 0 (Wla)
    asm volatile("fence.proxy.async.shared::cta;" ::: "memory");
    __syncthreads();

    const uint32_t aoff[5] = {SM_A0, SM_A0, SM_A0, SM_A1, SM_A1};
    const int wsel[5] = {0, 3, 4, 0, 2};
    float* const outp[5] = {g_c_net, g_hsrc1, g_hsrc2, g_c_cell, g_hsrc0};
    const int bvf[5] = {1, 0, 0, 1, 0};
    const uint32_t par[5] = {0, 0, 1, 1, 0};

#pragma unroll
    for (int i = 0; i < 5; i++) {
        asm volatile("tcgen05.fence::after_thread_sync;" ::: "memory");
        if (wid == 0 && elect1()) {
            issue_mma3(sb, aoff[i], SM_W5, tb + (i & 1) * 128);
            asm volatile(
                "tcgen05.commit.cta_group::1.mbarrier::arrive::one.shared::cluster.b64 [%0];"
                :: "r"(sb + 8 + (i & 1) * 8) : "memory");
        }
        if (i > 0)   // epilogue of previous layer overlaps this layer's MMA
            ep_store_global(tb + ((i - 1) & 1) * 128, outp[i - 1], bvf[i - 1],
                            row0, nrows, wid, lid);
        mbar_waitp(sb + 8 + (i & 1) * 8, par[i]);   // MMA_i done (W safe to overwrite)
        if (i < 4) {
            copy_w(g_wt + wsel[i + 1] * 32768, smem + SM_W5, tid);
            asm volatile("fence.proxy.async.shared::cta;" ::: "memory");
            __syncthreads();
        }
    }
    asm volatile("tcgen05.fence::after_thread_sync;" ::: "memory");
    ep_store_global(tb + 0, outp[4], bvf[4], row0, nrows, wid, lid);

    __syncthreads();
    if (wid == 0) {
        asm volatile("tcgen05.relinquish_alloc_permit.cta_group::1.sync.aligned;");
        asm volatile("tcgen05.dealloc.cta_group::1.sync.aligned.b32 %0, %1;" :: "r"(tb), "r"(512u));
    }
#endif
}

// ---------------- fused F-chain kernel ----------------
// net CTAs (blockIdx < gbn):  out_net = relu(C+ (relu(C+ relu(C+G0@W)@W) + G2)@W)
// cell CTAs: out_cell = relu(C + relu(C + (relu(C)+G1)@W)@W)      (C includes bvec)
// smem: A hi/lo 64KB, W (Wlb) 64KB, C fp32 tile padded stride 129 (66048 B)
#define SMC_A 1024
#define SMC_W (1024 + 65536)
#define SMC_C (1024 + 131072)
#define SMC_TOTAL (1024 + 131072 + 66048)

__global__ __launch_bounds__(256, 1) void chain_k(float* __restrict__ out, int nrows, int gbn) {
#if HAS_TCGEN05
    extern __shared__ char smem[];
    uint32_t sb = smem_u32(smem);
    int tid = threadIdx.x, wid = tid >> 5, lid = tid & 31;
    int isNet = blockIdx.x < gbn;
    int row0 = (isNet ? blockIdx.x : blockIdx.x - gbn) * 128;

    if (tid == 0)
        asm volatile("mbarrier.init.shared.b64 [%0], 1;" :: "r"(sb + 8) : "memory");
    if (wid == 0)
        asm volatile("tcgen05.alloc.cta_group::1.sync.aligned.shared::cta.b32 [%0], %1;"
                     :: "r"(sb), "r"(512u) : "memory");
    __syncthreads();
    uint32_t tb = *(volatile uint32_t*)smem;

    const float* Cg = isNet ? g_c_net : g_c_cell;
    float* Cs = (float*)(smem + SMC_C);
    // C tile into smem, padded stride 129 floats (conflict-free scalar reads)
#pragma unroll
    for (int q0 = 0; q0 < 16; q0++) {
        int q = tid + q0 * 256;
        int row = q >> 5, k = (q & 31) << 2;
        int gr = row0 + row;
        float4 v = make_float4(0.f, 0.f, 0.f, 0.f);
        if (gr < nrows) v = *(const float4*)(Cg + (size_t)gr * D + k);
        Cs[row * 129 + k] = v.x; Cs[row * 129 + k + 1] = v.y;
        Cs[row * 129 + k + 2] = v.z; Cs[row * 129 + k + 3] = v.w;
    }
    // first A:  net -> G0 ; cell -> relu(C)+G1
    if (isNet) load_split_A(g_G0, nullptr, 0, row0, nrows, smem + SMC_A, tid);
    else       load_split_A(g_c_cell, g_G1, 1, row0, nrows, smem + SMC_A, tid);
    copy_w(g_wt + 1 * 32768, smem + SMC_W, tid);   // Wlb
    asm volatile("fence.proxy.async.shared::cta;" ::: "memory");
    __syncthreads();

    int nl = isNet ? 3 : 2;
    int colb = (wid >> 2) * 64;
    int rloc = (wid & 3) * 32 + lid;
    int gr = row0 + rloc;

    for (int l = 0; l < nl; l++) {
        asm volatile("tcgen05.fence::after_thread_sync;" ::: "memory");
        if (wid == 0 && elect1()) {
            issue_mma3(sb, SMC_A, SMC_W, tb);
            asm volatile(
                "tcgen05.commit.cta_group::1.mbarrier::arrive::one.shared::cluster.b64 [%0];"
                :: "r"(sb + 8) : "memory");
        }
        mbar_waitp(sb + 8, (uint32_t)(l & 1));
        asm volatile("tcgen05.fence::after_thread_sync;" ::: "memory");

        uint32_t dr[64];
        tmem_ld_x32(dr, tb + colb);
        tmem_ld_x32(dr + 32, tb + colb + 32);
        asm volatile("tcgen05.wait::ld.sync.aligned;" ::: "memory");

        float o[64];
#pragma unroll
        for (int j = 0; j < 64; j++) {
            float v = __uint_as_float(dr[j]) + Cs[rloc * 129 + colb + j];
            o[j] = v > 0.f ? v : 0.f;
        }
        if (l == nl - 1) {
            if (gr < nrows) {
                float4* dp = (float4*)(out + (size_t)(isNet ? gr : nrows + gr) * D + colb);
#pragma unroll
                for (int j = 0; j < 16; j++)
                    dp[j] = make_float4(o[j * 4], o[j * 4 + 1], o[j * 4 + 2], o[j * 4 + 3]);
            }
            asm volatile("tcgen05.fence::before_thread_sync;" ::: "memory");
        } else {
            if (isNet && l == 1 && gr < nrows) {   // add G2 before final layer
                const float4* g2 = (const float4*)(g_G2 + (size_t)gr * D + colb);
#pragma unroll
                for (int j = 0; j < 16; j++) {
                    float4 u = g2[j];
                    o[j * 4] += u.x; o[j * 4 + 1] += u.y; o[j * 4 + 2] += u.z; o[j * 4 + 3] += u.w;
                }
            }
            // re-split into A smem (rows beyond nrows are exact zeros: acc=0, C=0)
#pragma unroll
            for (int j = 0; j < 16; j++) {
                float4 v = make_float4(o[j * 4], o[j * 4 + 1], o[j * 4 + 2], o[j * 4 + 3]);
                uint2 hi, lo;
                split4(v, hi, lo);
                int chunk = colb >> 6;
                uint32_t bo = rloc * 128 + (j * 4) * 2;
                uint32_t sw = bo ^ ((bo >> 3) & 0x70);
                *(uint2*)(smem + SMC_A + chunk * 16384 + sw) = hi;
                *(uint2*)(smem + SMC_A + chunk * 16384 + 32768 + sw) = lo;
            }
            asm volatile("fence.proxy.async.shared::cta;" ::: "memory");
            asm volatile("tcgen05.fence::before_thread_sync;" ::: "memory");
            __syncthreads();
        }
    }

    __syncthreads();
    if (wid == 0) {
        asm volatile("tcgen05.relinquish_alloc_permit.cta_group::1.sync.aligned;");
        asm volatile("tcgen05.dealloc.cta_group::1.sync.aligned.b32 %0, %1;" :: "r"(tb), "r"(512u));
    }
#endif
}

// ---------------- host launch ----------------
extern "C" void kernel_launch(void* const* d_in, const int* in_sizes, int n_in,
                              void* d_out, int out_size) {
    const float* x_net   = (const float*)d_in[0];
    const float* x_cell  = (const float*)d_in[1];
    const float* Wp_net  = (const float*)d_in[2];
    const float* Wp_cell = (const float*)d_in[3];
    const float* Wg0 = (const float*)d_in[4];
    const float* al0 = (const float*)d_in[5];
    const float* ar0 = (const float*)d_in[6];
    const float* Wg1 = (const float*)d_in[7];
    const float* al1 = (const float*)d_in[8];
    const float* ar1 = (const float*)d_in[9];
    const float* Wg2 = (const float*)d_in[10];
    const float* al2 = (const float*)d_in[11];
    const float* ar2 = (const float*)d_in[12];
    const float* Wl   = (const float*)d_in[13];
    const float* bias = (const float*)d_in[14];
    const int* src0 = (const int*)d_in[15];
    const int* dst0 = (const int*)d_in[16];
    const int* src1 = (const int*)d_in[17];
    const int* dst1 = (const int*)d_in[18];
    const int* src2 = (const int*)d_in[19];
    const int* dst2 = (const int*)d_in[20];

    int n  = in_sizes[0] / DIN;
    int E0 = in_sizes[15], E1 = in_sizes[17], E2 = in_sizes[19];
    float* out = (float*)d_out;
    int nd = n * D, gb = (n + 127) / 128;
    int Et = E0 + E1 + E2;

    cudaFuncSetAttribute(gemm5_k, cudaFuncAttributeMaxDynamicSharedMemorySize, SM5_TOTAL);
    cudaFuncSetAttribute(chain_k, cudaFuncAttributeMaxDynamicSharedMemorySize, SMC_TOTAL);

    // launch order chosen so launch #6 (ncu -s 5 -c 1) is gemm5_k
    vecprep_k<<<1, 128>>>(Wg0, al0, ar0, Wg1, al1, ar1, Wg2, al2, ar2, Wl, bias);       // 1
    wprep_all_k<<<(5 * 16384 + 255) / 256, 256>>>(Wl, Wg0, Wg1, Wg2);                   // 2
    fill_all_k<<<1024, 256>>>(n, nd / 4);                                               // 3
    projlog_k<<<(2 * n + 7) / 8, 256>>>(x_net, x_cell, Wp_net, Wp_cell, n);             // 4
    edge12m_k<<<(Et + 255) / 256, 256>>>(src0, dst0, src1, dst1, src2, dst2,
                                         E0, E1, E2);                                   // 5
    gemm5_k<<<gb, 256, SM5_TOTAL>>>(n);                                                 // 6 <- profiled
    edge3m_k<<<(Et * 32 + 255) / 256, 256>>>((const int*)d_in[15], (const int*)d_in[16],
                                             src1, dst1, src2, dst2, E0, E1, E2);       // 7
    chain_k<<<2 * gb, 256, SMC_TOTAL>>>(out, n, gb);                                    // 8
}

// round 15
// speedup vs baseline: 1.2276x; 1.0743x over previous
#include <cuda_runtime.h>
#include <cuda_bf16.h>
#include <math.h>
#include <stdint.h>

#define D 128
#define DIN 16
#define NMAX 100000
#define EMAX 600000
#define NTILES 782   // ceil(NMAX/128)

// tcgen05 is an arch-accelerated ("a") feature: only emit it in passes that
// target sm_103a / sm_100a. The plain compute_103 PTX fallback pass gets an
// empty body (never executed at runtime — the sm_103a cubin is used).
#if defined(__CUDA_ARCH_FEAT_SM103_ALL) || defined(__CUDA_ARCH_FEAT_SM100_ALL) || defined(__CUDA_ARCH_FEAT_SM101_ALL)
#define HAS_TCGEN05 1
#else
#define HAS_TCGEN05 0
#endif

// ---------------- scratch (static device globals; no allocations) ----------------
// h stored ONLY as pre-swizzled bf16 hi/lo 64KB tile images (gemm5's SMEM format)
__device__ uint8_t g_himg_net [(size_t)NTILES * 65536];
__device__ uint8_t g_himg_cell[(size_t)NTILES * 65536];
__device__ float g_c_net [(size_t)NMAX * D];   // feat@Wla^T + bvec  (net)
__device__ float g_c_cell[(size_t)NMAX * D];   // feat@Wla^T + bvec  (cell)
__device__ float g_hsrc0 [(size_t)NMAX * D];   // h_cell@Wg0^T
__device__ float g_hsrc1 [(size_t)NMAX * D];   // h_net @Wg1^T
__device__ float g_hsrc2 [(size_t)NMAX * D];   // h_net @Wg2^T
__device__ float g_G0    [(size_t)NMAX * D];
__device__ float g_G1    [(size_t)NMAX * D];
__device__ float g_G2    [(size_t)NMAX * D];
__device__ float g_se0[EMAX], g_se1[EMAX], g_se2[EMAX];
__device__ float g_dn0[NMAX], g_dn1[NMAX], g_dn2[NMAX];
__device__ float g_el0[NMAX], g_er0[NMAX], g_el1[NMAX], g_er1[NMAX], g_el2[NMAX], g_er2[NMAX];
// vecs rows: 0 wl0(cell) 1 wr0(net) 2 wl1(net) 3 wr1(cell) 4 wl2(net) 5 wr2(net) 6 bvec
__device__ float g_vecs[7 * D];
// x-space logit vectors: w16[r] = Wp_srctype(r)^T @ vecs[r]   (6 x 16)
__device__ float g_w16[6 * 16];
// pre-swizzled bf16 hi/lo weight tiles: idx 0=Wla 1=Wlb 2=Wg0 3=Wg1 4=Wg2 (32768 bf16 each)
__device__ __nv_bfloat16 g_wt[5 * 32768];

// ---------------- helpers ----------------
__device__ __forceinline__ uint32_t smem_u32(const void* p) {
    uint32_t r;
    asm("{ .reg .u64 t; cvta.to.shared.u64 t, %1; cvt.u32.u64 %0, t; }" : "=r"(r) : "l"(p));
    return r;
}
__device__ __forceinline__ uint32_t elect1() {
    uint32_t p;
    asm volatile("{\n\t.reg .pred p;\n\telect.sync _|p, 0xFFFFFFFF;\n\tselp.b32 %0, 1, 0, p;\n\t}" : "=r"(p));
    return p;
}
// SW128 K-major descriptor: layout=2, version=1, SBO=64, LBO=1
__device__ __forceinline__ uint64_t mkdesc(uint32_t addr) {
    return ((uint64_t)2 << 61) | ((uint64_t)1 << 46) | ((uint64_t)64 << 32) |
           ((uint64_t)1 << 16) | ((uint64_t)(addr >> 4) & 0x3FFF);
}
// idesc kind::f16: dtype=F32, atype=btype=BF16, N=128, M=128
#define MMA_IDESC 0x08200490u

__device__ __forceinline__ void mbar_waitp(uint32_t mbar, uint32_t parity) {
    asm volatile(
        "{\n\t.reg .pred P1;\n\t"
        "WAIT_LOOP_%=:\n\t"
        "mbarrier.try_wait.parity.acquire.cta.shared::cta.b64 P1, [%0], %1, 0x989680;\n\t"
        "@P1 bra.uni WAIT_DONE_%=;\n\t"
        "bra.uni WAIT_LOOP_%=;\n\t"
        "WAIT_DONE_%=:\n\t}"
        :: "r"(mbar), "r"(parity) : "memory");
}

__device__ __forceinline__ uint32_t pk2(float a, float b) {
    uint16_t ha = __bfloat16_as_ushort(__float2bfloat16(a));
    uint16_t hb = __bfloat16_as_ushort(__float2bfloat16(b));
    return (uint32_t)ha | ((uint32_t)hb << 16);
}
__device__ __forceinline__ void split4(float4 v, uint2& hi, uint2& lo) {
    __nv_bfloat16 h0 = __float2bfloat16(v.x), h1 = __float2bfloat16(v.y);
    __nv_bfloat16 h2 = __float2bfloat16(v.z), h3 = __float2bfloat16(v.w);
    hi.x = (uint32_t)__bfloat16_as_ushort(h0) | ((uint32_t)__bfloat16_as_ushort(h1) << 16);
    hi.y = (uint32_t)__bfloat16_as_ushort(h2) | ((uint32_t)__bfloat16_as_ushort(h3) << 16);
    lo.x = pk2(v.x - __bfloat162float(h0), v.y - __bfloat162float(h1));
    lo.y = pk2(v.z - __bfloat162float(h2), v.w - __bfloat162float(h3));
}

#if HAS_TCGEN05
__device__ __forceinline__ void mma_f16_ss(uint32_t d_tmem, uint64_t a_desc, uint64_t b_desc,
                                           uint32_t en) {
    asm volatile(
        "{\n\t.reg .pred p;\n\tsetp.ne.u32 p, %4, 0;\n\t"
        "tcgen05.mma.cta_group::1.kind::f16 [%0], %1, %2, %3, {%5, %5, %5, %5}, p;\n\t}"
        :: "r"(d_tmem), "l"(a_desc), "l"(b_desc), "r"(MMA_IDESC), "r"(en), "r"(0u)
        : "memory");
}
__device__ __forceinline__ void tmem_ld_x32(uint32_t* r, uint32_t a) {
    asm volatile("tcgen05.ld.sync.aligned.32x32b.x32.b32 "
        "{%0,%1,%2,%3,%4,%5,%6,%7,%8,%9,%10,%11,%12,%13,%14,%15,"
        "%16,%17,%18,%19,%20,%21,%22,%23,%24,%25,%26,%27,%28,%29,%30,%31}, [%32];"
        : "=r"(r[0]), "=r"(r[1]), "=r"(r[2]), "=r"(r[3]), "=r"(r[4]), "=r"(r[5]),
          "=r"(r[6]), "=r"(r[7]), "=r"(r[8]), "=r"(r[9]), "=r"(r[10]), "=r"(r[11]),
          "=r"(r[12]), "=r"(r[13]), "=r"(r[14]), "=r"(r[15]), "=r"(r[16]), "=r"(r[17]),
          "=r"(r[18]), "=r"(r[19]), "=r"(r[20]), "=r"(r[21]), "=r"(r[22]), "=r"(r[23]),
          "=r"(r[24]), "=r"(r[25]), "=r"(r[26]), "=r"(r[27]), "=r"(r[28]), "=r"(r[29]),
          "=r"(r[30]), "=r"(r[31])
        : "r"(a));
}
// 3-pass split-bf16 MMA for one 128x128x128 layer: Ah*Wh + Ah*Wl + Al*Wh
__device__ __forceinline__ void issue_mma3(uint32_t sb, uint32_t aoff, uint32_t woff,
                                           uint32_t tb_d) {
    int first = 1;
#pragma unroll
    for (int pass = 0; pass < 3; pass++) {
        uint32_t a = (pass == 2) ? aoff + 32768u : aoff;
        uint32_t w = (pass == 1) ? woff + 32768u : woff;
#pragma unroll
        for (int c = 0; c < 2; c++) {
            uint64_t ad = mkdesc(sb + a + c * 16384);
            uint64_t bd = mkdesc(sb + w + c * 16384);
#pragma unroll
            for (int ks = 0; ks < 4; ks++) {
                mma_f16_ss(tb_d, ad + ks * 2, bd + ks * 2, first ? 0u : 1u);
                first = 0;
            }
        }
    }
}
// load 128xD fp32 rows (opt relu on first, opt add second), split, store swizzled hi/lo
__device__ __forceinline__ void load_split_A(const float* __restrict__ A1,
                                             const float* __restrict__ A2, int reluFirst,
                                             int row0, int nrows, char* abase, int tid) {
#pragma unroll
    for (int q0 = 0; q0 < 16; q0++) {
        int q = tid + q0 * 256;
        int row = q >> 5, k = (q & 31) << 2;
        int gr = row0 + row;
        float4 v = make_float4(0.f, 0.f, 0.f, 0.f);
        if (gr < nrows) {
            v = *(const float4*)(A1 + (size_t)gr * D + k);
            if (reluFirst) {
                v.x = fmaxf(v.x, 0.f); v.y = fmaxf(v.y, 0.f);
                v.z = fmaxf(v.z, 0.f); v.w = fmaxf(v.w, 0.f);
            }
            if (A2) {
                float4 u = *(const float4*)(A2 + (size_t)gr * D + k);
                v.x += u.x; v.y += u.y; v.z += u.z; v.w += u.w;
            }
        }
        uint2 hi, lo;
        split4(v, hi, lo);
        int chunk = k >> 6, kin = k & 63;
        uint32_t bo = row * 128 + kin * 2;
        uint32_t sw = bo ^ ((bo >> 3) & 0x70);
        *(uint2*)(abase + chunk * 16384 + sw) = hi;
        *(uint2*)(abase + chunk * 16384 + 32768 + sw) = lo;
    }
}
// plain 64KB tile copy (global image -> smem), same layout
__device__ __forceinline__ void copy_w(const void* __restrict__ Wt, char* wbase, int tid) {
    const float4* ws = (const float4*)Wt;
    float4* wd = (float4*)wbase;
#pragma unroll
    for (int q = 0; q < 16; q++) wd[tid + q * 256] = ws[tid + q * 256];
}
// 8-warp epilogue to global: warps (w>>2) take col halves, rows = (w&3)*32+lane
__device__ __forceinline__ void ep_store_global(uint32_t tb_d, float* __restrict__ outp,
                                                int addBvec, int row0, int nrows,
                                                int wid, int lid) {
    int colb = (wid >> 2) * 64;
    int rloc = (wid & 3) * 32 + lid;
    int gr = row0 + rloc;
    uint32_t dr[64];
    tmem_ld_x32(dr, tb_d + colb);
    tmem_ld_x32(dr + 32, tb_d + colb + 32);
    asm volatile("tcgen05.wait::ld.sync.aligned;" ::: "memory");
    if (gr < nrows) {
        float4* cp = (float4*)(outp + (size_t)gr * D + colb);
#pragma unroll
        for (int j = 0; j < 16; j++) {
            float4 f = make_float4(__uint_as_float(dr[j * 4]), __uint_as_float(dr[j * 4 + 1]),
                                   __uint_as_float(dr[j * 4 + 2]), __uint_as_float(dr[j * 4 + 3]));
            if (addBvec) {
                f.x += g_vecs[6 * D + colb + j * 4];
                f.y += g_vecs[6 * D + colb + j * 4 + 1];
                f.z += g_vecs[6 * D + colb + j * 4 + 2];
                f.w += g_vecs[6 * D + colb + j * 4 + 3];
            }
            cp[j] = f;
        }
    }
    asm volatile("tcgen05.fence::before_thread_sync;" ::: "memory");
}
#endif  // HAS_TCGEN05

// ---------------- small utility kernels ----------------
__global__ void vecprep_k(const float* Wg0, const float* al0, const float* ar0,
                          const float* Wg1, const float* al1, const float* ar1,
                          const float* Wg2, const float* al2, const float* ar2,
                          const float* Wl, const float* bias,
                          const float* Wpn, const float* Wpc) {
    int k = threadIdx.x;
    float s;
    s = 0.f; for (int j = 0; j < D; j++) s += al0[j] * Wg0[j * D + k]; g_vecs[0 * D + k] = s;
    s = 0.f; for (int j = 0; j < D; j++) s += ar0[j] * Wg0[j * D + k]; g_vecs[1 * D + k] = s;
    s = 0.f; for (int j = 0; j < D; j++) s += al1[j] * Wg1[j * D + k]; g_vecs[2 * D + k] = s;
    s = 0.f; for (int j = 0; j < D; j++) s += ar1[j] * Wg1[j * D + k]; g_vecs[3 * D + k] = s;
    s = 0.f; for (int j = 0; j < D; j++) s += al2[j] * Wg2[j * D + k]; g_vecs[4 * D + k] = s;
    s = 0.f; for (int j = 0; j < D; j++) s += ar2[j] * Wg2[j * D + k]; g_vecs[5 * D + k] = s;
    s = 0.f; for (int j = 0; j < D; j++) s += Wl[(size_t)k * 2 * D + D + j] * bias[j]; g_vecs[6 * D + k] = s;
    __syncthreads();
    // x-space logit vectors: w16[r][k16] = sum_d Wp_src(r)[d][k16] * vecs[r][d]
    if (k < 16) {
#pragma unroll
        for (int r = 0; r < 6; r++) {
            const float* Wp = (r == 0 || r == 3) ? Wpc : Wpn;   // src types: cell,net,net,cell,net,net
            float acc = 0.f;
            for (int d = 0; d < D; d++) acc += Wp[d * DIN + k] * g_vecs[r * D + d];
            g_w16[r * 16 + k] = acc;
        }
    }
}

// weight prep: split fp32 into bf16 hi/lo, pre-swizzled SMEM tile images (5 weights)
__global__ void wprep_all_k(const float* __restrict__ Wl, const float* __restrict__ Wg0,
                            const float* __restrict__ Wg1, const float* __restrict__ Wg2) {
    int gid = blockIdx.x * blockDim.x + threadIdx.x;
    if (gid >= 5 * 16384) return;
    int w = gid >> 14, i = gid & 16383;
    const float* src; int ld, off;
    if (w == 0)      { src = Wl;  ld = 256; off = 0;   }
    else if (w == 1) { src = Wl;  ld = 256; off = 128; }
    else if (w == 2) { src = Wg0; ld = 128; off = 0;   }
    else if (w == 3) { src = Wg1; ld = 128; off = 0;   }
    else             { src = Wg2; ld = 128; off = 0;   }
    int j = i >> 7, k = i & 127;
    float v = src[(size_t)j * ld + off + k];
    __nv_bfloat16 h = __float2bfloat16(v);
    __nv_bfloat16 l = __float2bfloat16(v - __bfloat162float(h));
    int chunk = k >> 6;
    uint32_t bo = j * 128 + (k & 63) * 2;
    uint32_t sw = bo ^ ((bo >> 3) & 0x70);
    char* hb = (char*)g_wt + w * 65536 + chunk * 16384;
    *(__nv_bfloat16*)(hb + sw) = h;
    *(__nv_bfloat16*)(hb + 32768 + sw) = l;
}

// ---------------- fused projection + logits + zero-init: register-resident Wp ----------------
// One warp processes 32 consecutive nodes of one type. Wp columns live in registers
// (4 cols x 16 per lane); x rows broadcast via shfl. h written directly as split-bf16
// swizzled tile images. Logits computed per-lane in x-space (w16 = Wp^T @ vec).
// Net warps also zero G0/G1/G2 rows and dn0/dn1/dn2.
__global__ __launch_bounds__(256) void projlog_k(
    const float* __restrict__ xn, const float* __restrict__ xc,
    const float* __restrict__ Wpn, const float* __restrict__ Wpc, int n, int nwpt) {
    __shared__ float Ws[2][128 * 17];
    __shared__ float w16s[96];
    int tid = threadIdx.x;
    for (int i = tid; i < 2048; i += 256) {
        int d = i >> 4, k = i & 15;
        Ws[0][d * 17 + k] = Wpn[i];
        Ws[1][d * 17 + k] = Wpc[i];
    }
    for (int i = tid; i < 96; i += 256) w16s[i] = g_w16[i];
    __syncthreads();

    int gw = blockIdx.x * 8 + (tid >> 5);
    if (gw >= 2 * nwpt) return;
    int lane = tid & 31;
    int type = gw >= nwpt ? 1 : 0;
    int base = (gw - type * nwpt) * 32;

    // Wp columns 4*lane..4*lane+3 into registers (one-time smem read)
    float Wreg[4][16];
#pragma unroll
    for (int c = 0; c < 4; c++)
#pragma unroll
        for (int k = 0; k < 16; k++) Wreg[c][k] = Ws[type][(4 * lane + c) * 17 + k];

    // lane's own x row
    int mynode = base + lane;
    float x[16];
    {
        const float* xsrc = type ? xc : xn;
        if (mynode < n) {
            const float4* x4 = (const float4*)(xsrc + (size_t)mynode * DIN);
#pragma unroll
            for (int i = 0; i < 4; i++) {
                float4 v = x4[i];
                x[i * 4] = v.x; x[i * 4 + 1] = v.y; x[i * 4 + 2] = v.z; x[i * 4 + 3] = v.w;
            }
        } else {
#pragma unroll
            for (int i = 0; i < 16; i++) x[i] = 0.f;
        }
    }

    // logits for own node (x-space), plus dn zero (net warps own the node-id space)
    if (mynode < n) {
        if (type == 0) {
            float s1 = 0.f, s2 = 0.f, s4 = 0.f, s5 = 0.f;
#pragma unroll
            for (int k = 0; k < 16; k++) {
                s1 = fmaf(x[k], w16s[1 * 16 + k], s1);
                s2 = fmaf(x[k], w16s[2 * 16 + k], s2);
                s4 = fmaf(x[k], w16s[4 * 16 + k], s4);
                s5 = fmaf(x[k], w16s[5 * 16 + k], s5);
            }
            g_er0[mynode] = s1; g_el1[mynode] = s2; g_el2[mynode] = s4; g_er2[mynode] = s5;
            g_dn0[mynode] = 0.f; g_dn1[mynode] = 0.f; g_dn2[mynode] = 0.f;
        } else {
            float s0 = 0.f, s3 = 0.f;
#pragma unroll
            for (int k = 0; k < 16; k++) {
                s0 = fmaf(x[k], w16s[0 * 16 + k], s0);
                s3 = fmaf(x[k], w16s[3 * 16 + k], s3);
            }
            g_el0[mynode] = s0; g_er1[mynode] = s3;
        }
    }

    uint8_t* img = type ? g_himg_cell : g_himg_net;
    float4 z4 = make_float4(0.f, 0.f, 0.f, 0.f);
    for (int s = 0; s < 32; s++) {
        int node = base + s;
        float h[4] = {0.f, 0.f, 0.f, 0.f};
#pragma unroll
        for (int k = 0; k < 16; k++) {
            float xk = __shfl_sync(0xffffffffu, x[k], s);
            h[0] = fmaf(xk, Wreg[0][k], h[0]);
            h[1] = fmaf(xk, Wreg[1][k], h[1]);
            h[2] = fmaf(xk, Wreg[2][k], h[2]);
            h[3] = fmaf(xk, Wreg[3][k], h[3]);
        }
        // store split-bf16 into swizzled tile image (pad rows beyond n are zeros)
        uint2 hi, lo;
        split4(make_float4(h[0], h[1], h[2], h[3]), hi, lo);
        char* tb = (char*)img + (size_t)(node >> 7) * 65536;
        int chunk = lane >> 4;
        uint32_t bo = (node & 127) * 128 + ((4 * lane) & 63) * 2;
        uint32_t sw = bo ^ ((bo >> 3) & 0x70);
        *(uint2*)(tb + chunk * 16384 + sw) = hi;
        *(uint2*)(tb + chunk * 16384 + 32768 + sw) = lo;
        // zero G rows (net warps only; id space shared)
        if (type == 0 && node < n) {
            ((float4*)(g_G0 + (size_t)node * D))[lane] = z4;
            ((float4*)(g_G1 + (size_t)node * D))[lane] = z4;
            ((float4*)(g_G2 + (size_t)node * D))[lane] = z4;
        }
    }
}

// fused edge softmax numerator + denominator, all 3 relations in one launch
__global__ void edge12m_k(const int* __restrict__ src0, const int* __restrict__ dst0,
                          const int* __restrict__ src1, const int* __restrict__ dst1,
                          const int* __restrict__ src2, const int* __restrict__ dst2,
                          int E0, int E1, int E2) {
    int e = blockIdx.x * blockDim.x + threadIdx.x;
    const int *src, *dst; const float *elv, *erv; float *se, *den;
    if (e < E0) {
        src = src0; dst = dst0; elv = g_el0; erv = g_er0; se = g_se0; den = g_dn0;
    } else if (e < E0 + E1) {
        e -= E0;
        src = src1; dst = dst1; elv = g_el1; erv = g_er1; se = g_se1; den = g_dn1;
    } else if (e < E0 + E1 + E2) {
        e -= E0 + E1;
        src = src2; dst = dst2; elv = g_el2; erv = g_er2; se = g_se2; den = g_dn2;
    } else return;
    float s = elv[src[e]] + erv[dst[e]];
    s = s > 0.f ? s : 0.2f * s;
    float ex = expf(s);
    se[e] = ex;
    atomicAdd(&den[dst[e]], ex);
}

// weighted scatter for all 3 relations: G[dst] += alpha * hsrc[src]; warp/edge, float4 atomics
__global__ void edge3m_k(const int* __restrict__ src0, const int* __restrict__ dst0,
                         const int* __restrict__ src1, const int* __restrict__ dst1,
                         const int* __restrict__ src2, const int* __restrict__ dst2,
                         int E0, int E1, int E2) {
    int t = blockIdx.x * blockDim.x + threadIdx.x;
    int e = t >> 5, lane = t & 31;
    const int *src, *dst; const float *se, *den, *hs; float *G;
    if (e < E0) {
        src = src0; dst = dst0; se = g_se0; den = g_dn0; hs = g_hsrc0; G = g_G0;
    } else if (e < E0 + E1) {
        e -= E0;
        src = src1; dst = dst1; se = g_se1; den = g_dn1; hs = g_hsrc1; G = g_G1;
    } else if (e < E0 + E1 + E2) {
        e -= E0 + E1;
        src = src2; dst = dst2; se = g_se2; den = g_dn2; hs = g_hsrc2; G = g_G2;
    } else return;
    int s = src[e], d = dst[e];
    float alpha = se[e] / den[d];
    float4 v = ((const float4*)(hs + (size_t)s * D))[lane];
    v.x *= alpha; v.y *= alpha; v.z *= alpha; v.w *= alpha;
    atomicAdd(((float4*)(G + (size_t)d * D)) + lane, v);
}

// ---------------- fused 5-GEMM kernel (c_net, hs1, hs2, c_cell, hs0) ----------------
// smem: [0] tmem ptr, [8],[16] mbarriers, A_net hi/lo 64KB, A_cell hi/lo 64KB, W 64KB
#define SM_A0 1024
#define SM_A1 (1024 + 65536)
#define SM_W5 (1024 + 131072)
#define SM5_TOTAL (1024 + 196608)

__global__ __launch_bounds__(256, 1) void gemm5_k(int nrows) {
#if HAS_TCGEN05
    extern __shared__ char smem[];
    uint32_t sb = smem_u32(smem);
    int tid = threadIdx.x, wid = tid >> 5, lid = tid & 31;
    int row0 = blockIdx.x * 128;

    if (tid == 0) {
        asm volatile("mbarrier.init.shared.b64 [%0], 1;" :: "r"(sb + 8) : "memory");
        asm volatile("mbarrier.init.shared.b64 [%0], 1;" :: "r"(sb + 16) : "memory");
    }
    if (wid == 0)
        asm volatile("tcgen05.alloc.cta_group::1.sync.aligned.shared::cta.b32 [%0], %1;"
                     :: "r"(sb), "r"(512u) : "memory");
    __syncthreads();
    uint32_t tb = *(volatile uint32_t*)smem;

    // A tiles arrive pre-split/pre-swizzled from projlog — plain 64KB copies
    copy_w(g_himg_net  + (size_t)blockIdx.x * 65536, smem + SM_A0, tid);
    copy_w(g_himg_cell + (size_t)blockIdx.x * 65536, smem + SM_A1, tid);
    copy_w(g_wt + 0 * 32768, smem + SM_W5, tid);   // W for layer 0 (Wla)
    asm volatile("fence.proxy.async.shared::cta;" ::: "memory");
    __syncthreads();

    const uint32_t aoff[5] = {SM_A0, SM_A0, SM_A0, SM_A1, SM_A1};
    const int wsel[5] = {0, 3, 4, 0, 2};
    float* const outp[5] = {g_c_net, g_hsrc1, g_hsrc2, g_c_cell, g_hsrc0};
    const int bvf[5] = {1, 0, 0, 1, 0};
    const uint32_t par[5] = {0, 0, 1, 1, 0};

#pragma unroll
    for (int i = 0; i < 5; i++) {
        asm volatile("tcgen05.fence::after_thread_sync;" ::: "memory");
        if (wid == 0 && elect1()) {
            issue_mma3(sb, aoff[i], SM_W5, tb + (i & 1) * 128);
            asm volatile(
                "tcgen05.commit.cta_group::1.mbarrier::arrive::one.shared::cluster.b64 [%0];"
                :: "r"(sb + 8 + (i & 1) * 8) : "memory");
        }
        if (i > 0)   // epilogue of previous layer overlaps this layer's MMA
            ep_store_global(tb + ((i - 1) & 1) * 128, outp[i - 1], bvf[i - 1],
                            row0, nrows, wid, lid);
        mbar_waitp(sb + 8 + (i & 1) * 8, par[i]);   // MMA_i done (W safe to overwrite)
        if (i < 4) {
            copy_w(g_wt + wsel[i + 1] * 32768, smem + SM_W5, tid);
            asm volatile("fence.proxy.async.shared::cta;" ::: "memory");
            __syncthreads();
        }
    }
    asm volatile("tcgen05.fence::after_thread_sync;" ::: "memory");
    ep_store_global(tb + 0, outp[4], bvf[4], row0, nrows, wid, lid);

    __syncthreads();
    if (wid == 0) {
        asm volatile("tcgen05.relinquish_alloc_permit.cta_group::1.sync.aligned;");
        asm volatile("tcgen05.dealloc.cta_group::1.sync.aligned.b32 %0, %1;" :: "r"(tb), "r"(512u));
    }
#endif
}

// ---------------- fused F-chain kernel ----------------
// net CTAs (blockIdx < gbn):  out_net = relu(C+ (relu(C+ relu(C+G0@W)@W) + G2)@W)
// cell CTAs: out_cell = relu(C + relu(C + (relu(C)+G1)@W)@W)      (C includes bvec)
// smem: A hi/lo 64KB, W (Wlb) 64KB, C fp32 tile padded stride 129 (66048 B)
#define SMC_A 1024
#define SMC_W (1024 + 65536)
#define SMC_C (1024 + 131072)
#define SMC_TOTAL (1024 + 131072 + 66048)

__global__ __launch_bounds__(256, 1) void chain_k(float* __restrict__ out, int nrows, int gbn) {
#if HAS_TCGEN05
    extern __shared__ char smem[];
    uint32_t sb = smem_u32(smem);
    int tid = threadIdx.x, wid = tid >> 5, lid = tid & 31;
    int isNet = blockIdx.x < gbn;
    int row0 = (isNet ? blockIdx.x : blockIdx.x - gbn) * 128;

    if (tid == 0)
        asm volatile("mbarrier.init.shared.b64 [%0], 1;" :: "r"(sb + 8) : "memory");
    if (wid == 0)
        asm volatile("tcgen05.alloc.cta_group::1.sync.aligned.shared::cta.b32 [%0], %1;"
                     :: "r"(sb), "r"(512u) : "memory");
    __syncthreads();
    uint32_t tb = *(volatile uint32_t*)smem;

    const float* Cg = isNet ? g_c_net : g_c_cell;
    float* Cs = (float*)(smem + SMC_C);
    // C tile into smem, padded stride 129 floats (conflict-free scalar reads)
#pragma unroll
    for (int q0 = 0; q0 < 16; q0++) {
        int q = tid + q0 * 256;
        int row = q >> 5, k = (q & 31) << 2;
        int gr = row0 + row;
        float4 v = make_float4(0.f, 0.f, 0.f, 0.f);
        if (gr < nrows) v = *(const float4*)(Cg + (size_t)gr * D + k);
        Cs[row * 129 + k] = v.x; Cs[row * 129 + k + 1] = v.y;
        Cs[row * 129 + k + 2] = v.z; Cs[row * 129 + k + 3] = v.w;
    }
    // first A:  net -> G0 ; cell -> relu(C)+G1
    if (isNet) load_split_A(g_G0, nullptr, 0, row0, nrows, smem + SMC_A, tid);
    else       load_split_A(g_c_cell, g_G1, 1, row0, nrows, smem + SMC_A, tid);
    copy_w(g_wt + 1 * 32768, smem + SMC_W, tid);   // Wlb
    asm volatile("fence.proxy.async.shared::cta;" ::: "memory");
    __syncthreads();

    int nl = isNet ? 3 : 2;
    int colb = (wid >> 2) * 64;
    int rloc = (wid & 3) * 32 + lid;
    int gr = row0 + rloc;

    for (int l = 0; l < nl; l++) {
        asm volatile("tcgen05.fence::after_thread_sync;" ::: "memory");
        if (wid == 0 && elect1()) {
            issue_mma3(sb, SMC_A, SMC_W, tb);
            asm volatile(
                "tcgen05.commit.cta_group::1.mbarrier::arrive::one.shared::cluster.b64 [%0];"
                :: "r"(sb + 8) : "memory");
        }
        mbar_waitp(sb + 8, (uint32_t)(l & 1));
        asm volatile("tcgen05.fence::after_thread_sync;" ::: "memory");

        uint32_t dr[64];
        tmem_ld_x32(dr, tb + colb);
        tmem_ld_x32(dr + 32, tb + colb + 32);
        asm volatile("tcgen05.wait::ld.sync.aligned;" ::: "memory");

        float o[64];
#pragma unroll
        for (int j = 0; j < 64; j++) {
            float v = __uint_as_float(dr[j]) + Cs[rloc * 129 + colb + j];
            o[j] = v > 0.f ? v : 0.f;
        }
        if (l == nl - 1) {
            if (gr < nrows) {
                float4* dp = (float4*)(out + (size_t)(isNet ? gr : nrows + gr) * D + colb);
#pragma unroll
                for (int j = 0; j < 16; j++)
                    dp[j] = make_float4(o[j * 4], o[j * 4 + 1], o[j * 4 + 2], o[j * 4 + 3]);
            }
            asm volatile("tcgen05.fence::before_thread_sync;" ::: "memory");
        } else {
            if (isNet && l == 1 && gr < nrows) {   // add G2 before final layer
                const float4* g2 = (const float4*)(g_G2 + (size_t)gr * D + colb);
#pragma unroll
                for (int j = 0; j < 16; j++) {
                    float4 u = g2[j];
                    o[j * 4] += u.x; o[j * 4 + 1] += u.y; o[j * 4 + 2] += u.z; o[j * 4 + 3] += u.w;
                }
            }
            // re-split into A smem (rows beyond nrows are exact zeros: acc=0, C=0)
#pragma unroll
            for (int j = 0; j < 16; j++) {
                float4 v = make_float4(o[j * 4], o[j * 4 + 1], o[j * 4 + 2], o[j * 4 + 3]);
                uint2 hi, lo;
                split4(v, hi, lo);
                int chunk = colb >> 6;
                uint32_t bo = rloc * 128 + (j * 4) * 2;
                uint32_t sw = bo ^ ((bo >> 3) & 0x70);
                *(uint2*)(smem + SMC_A + chunk * 16384 + sw) = hi;
                *(uint2*)(smem + SMC_A + chunk * 16384 + 32768 + sw) = lo;
            }
            asm volatile("fence.proxy.async.shared::cta;" ::: "memory");
            asm volatile("tcgen05.fence::before_thread_sync;" ::: "memory");
            __syncthreads();
        }
    }

    __syncthreads();
    if (wid == 0) {
        asm volatile("tcgen05.relinquish_alloc_permit.cta_group::1.sync.aligned;");
        asm volatile("tcgen05.dealloc.cta_group::1.sync.aligned.b32 %0, %1;" :: "r"(tb), "r"(512u));
    }
#endif
}

// ---------------- host launch ----------------
extern "C" void kernel_launch(void* const* d_in, const int* in_sizes, int n_in,
                              void* d_out, int out_size) {
    const float* x_net   = (const float*)d_in[0];
    const float* x_cell  = (const float*)d_in[1];
    const float* Wp_net  = (const float*)d_in[2];
    const float* Wp_cell = (const float*)d_in[3];
    const float* Wg0 = (const float*)d_in[4];
    const float* al0 = (const float*)d_in[5];
    const float* ar0 = (const float*)d_in[6];
    const float* Wg1 = (const float*)d_in[7];
    const float* al1 = (const float*)d_in[8];
    const float* ar1 = (const float*)d_in[9];
    const float* Wg2 = (const float*)d_in[10];
    const float* al2 = (const float*)d_in[11];
    const float* ar2 = (const float*)d_in[12];
    const float* Wl   = (const float*)d_in[13];
    const float* bias = (const float*)d_in[14];
    const int* src0 = (const int*)d_in[15];
    const int* dst0 = (const int*)d_in[16];
    const int* src1 = (const int*)d_in[17];
    const int* dst1 = (const int*)d_in[18];
    const int* src2 = (const int*)d_in[19];
    const int* dst2 = (const int*)d_in[20];

    int n  = in_sizes[0] / DIN;
    int E0 = in_sizes[15], E1 = in_sizes[17], E2 = in_sizes[19];
    float* out = (float*)d_out;
    int gb = (n + 127) / 128;
    int nwpt = gb * 4;           // warps per node type (covers full tile padding)
    int Et = E0 + E1 + E2;

    cudaFuncSetAttribute(gemm5_k, cudaFuncAttributeMaxDynamicSharedMemorySize, SM5_TOTAL);
    cudaFuncSetAttribute(chain_k, cudaFuncAttributeMaxDynamicSharedMemorySize, SMC_TOTAL);

    // launch order: #6 (ncu -s 5 -c 1) is edge3m_k, the dominant unknown
    vecprep_k<<<1, 128>>>(Wg0, al0, ar0, Wg1, al1, ar1, Wg2, al2, ar2, Wl, bias,
                          Wp_net, Wp_cell);                                             // 1
    wprep_all_k<<<(5 * 16384 + 255) / 256, 256>>>(Wl, Wg0, Wg1, Wg2);                   // 2
    projlog_k<<<(2 * nwpt + 7) / 8, 256>>>(x_net, x_cell, Wp_net, Wp_cell, n, nwpt);    // 3
    edge12m_k<<<(Et + 255) / 256, 256>>>(src0, dst0, src1, dst1, src2, dst2,
                                         E0, E1, E2);                                   // 4
    gemm5_k<<<gb, 256, SM5_TOTAL>>>(n);                                                 // 5
    edge3m_k<<<(Et * 32 + 255) / 256, 256>>>(src0, dst0, src1, dst1, src2, dst2,
                                             E0, E1, E2);                               // 6 <- profiled
    chain_k<<<2 * gb, 256, SMC_TOTAL>>>(out, n, gb);                                    // 7
}

// round 16
// speedup vs baseline: 1.2396x; 1.0098x over previous
#include <cuda_runtime.h>
#include <cuda_bf16.h>
#include <math.h>
#include <stdint.h>

#define D 128
#define DIN 16
#define NMAX 100000
#define EMAX 600000
#define NTILES 782   // ceil(NMAX/128)

// tcgen05 is an arch-accelerated ("a") feature: only emit it in passes that
// target sm_103a / sm_100a. The plain compute_103 PTX fallback pass gets an
// empty body (never executed at runtime — the sm_103a cubin is used).
#if defined(__CUDA_ARCH_FEAT_SM103_ALL) || defined(__CUDA_ARCH_FEAT_SM100_ALL) || defined(__CUDA_ARCH_FEAT_SM101_ALL)
#define HAS_TCGEN05 1
#else
#define HAS_TCGEN05 0
#endif

// ---------------- scratch (static device globals; no allocations) ----------------
// h stored ONLY as pre-swizzled bf16 hi/lo 64KB tile images (gemm5's SMEM format)
__device__ uint8_t g_himg_net [(size_t)NTILES * 65536];
__device__ uint8_t g_himg_cell[(size_t)NTILES * 65536];
__device__ float g_c_net [(size_t)NMAX * D];   // feat@Wla^T + bvec  (net)
__device__ float g_c_cell[(size_t)NMAX * D];   // feat@Wla^T + bvec  (cell)
__device__ float g_hsrc0 [(size_t)NMAX * D];   // h_cell@Wg0^T
__device__ float g_hsrc1 [(size_t)NMAX * D];   // h_net @Wg1^T
__device__ float g_hsrc2 [(size_t)NMAX * D];   // h_net @Wg2^T
__device__ float g_G0    [(size_t)NMAX * D];
__device__ float g_G1    [(size_t)NMAX * D];
__device__ float g_G2    [(size_t)NMAX * D];
__device__ float g_se0[EMAX], g_se1[EMAX], g_se2[EMAX];
__device__ float g_dn0[NMAX], g_dn1[NMAX], g_dn2[NMAX];
__device__ float g_el0[NMAX], g_er0[NMAX], g_el1[NMAX], g_er1[NMAX], g_el2[NMAX], g_er2[NMAX];
// vecs rows: 0 wl0(cell) 1 wr0(net) 2 wl1(net) 3 wr1(cell) 4 wl2(net) 5 wr2(net) 6 bvec
__device__ float g_vecs[7 * D];
// x-space logit vectors: w16[r] = Wp_srctype(r)^T @ vecs[r]   (6 x 16)
__device__ float g_w16[6 * 16];
// pre-swizzled bf16 hi/lo weight tiles: idx 0=Wla 1=Wlb 2=Wg0 3=Wg1 4=Wg2 (32768 bf16 each)
__device__ __nv_bfloat16 g_wt[5 * 32768];

// ---------------- helpers ----------------
__device__ __forceinline__ uint32_t smem_u32(const void* p) {
    uint32_t r;
    asm("{ .reg .u64 t; cvta.to.shared.u64 t, %1; cvt.u32.u64 %0, t; }" : "=r"(r) : "l"(p));
    return r;
}
__device__ __forceinline__ uint32_t elect1() {
    uint32_t p;
    asm volatile("{\n\t.reg .pred p;\n\telect.sync _|p, 0xFFFFFFFF;\n\tselp.b32 %0, 1, 0, p;\n\t}" : "=r"(p));
    return p;
}
// SW128 K-major descriptor: layout=2, version=1, SBO=64, LBO=1
__device__ __forceinline__ uint64_t mkdesc(uint32_t addr) {
    return ((uint64_t)2 << 61) | ((uint64_t)1 << 46) | ((uint64_t)64 << 32) |
           ((uint64_t)1 << 16) | ((uint64_t)(addr >> 4) & 0x3FFF);
}
// idesc kind::f16: dtype=F32, atype=btype=BF16, N=128, M=128
#define MMA_IDESC 0x08200490u

__device__ __forceinline__ void mbar_waitp(uint32_t mbar, uint32_t parity) {
    asm volatile(
        "{\n\t.reg .pred P1;\n\t"
        "WAIT_LOOP_%=:\n\t"
        "mbarrier.try_wait.parity.acquire.cta.shared::cta.b64 P1, [%0], %1, 0x989680;\n\t"
        "@P1 bra.uni WAIT_DONE_%=;\n\t"
        "bra.uni WAIT_LOOP_%=;\n\t"
        "WAIT_DONE_%=:\n\t}"
        :: "r"(mbar), "r"(parity) : "memory");
}

__device__ __forceinline__ uint32_t pk2(float a, float b) {
    uint16_t ha = __bfloat16_as_ushort(__float2bfloat16(a));
    uint16_t hb = __bfloat16_as_ushort(__float2bfloat16(b));
    return (uint32_t)ha | ((uint32_t)hb << 16);
}
__device__ __forceinline__ void split4(float4 v, uint2& hi, uint2& lo) {
    __nv_bfloat16 h0 = __float2bfloat16(v.x), h1 = __float2bfloat16(v.y);
    __nv_bfloat16 h2 = __float2bfloat16(v.z), h3 = __float2bfloat16(v.w);
    hi.x = (uint32_t)__bfloat16_as_ushort(h0) | ((uint32_t)__bfloat16_as_ushort(h1) << 16);
    hi.y = (uint32_t)__bfloat16_as_ushort(h2) | ((uint32_t)__bfloat16_as_ushort(h3) << 16);
    lo.x = pk2(v.x - __bfloat162float(h0), v.y - __bfloat162float(h1));
    lo.y = pk2(v.z - __bfloat162float(h2), v.w - __bfloat162float(h3));
}

#if HAS_TCGEN05
__device__ __forceinline__ void mma_f16_ss(uint32_t d_tmem, uint64_t a_desc, uint64_t b_desc,
                                           uint32_t en) {
    asm volatile(
        "{\n\t.reg .pred p;\n\tsetp.ne.u32 p, %4, 0;\n\t"
        "tcgen05.mma.cta_group::1.kind::f16 [%0], %1, %2, %3, {%5, %5, %5, %5}, p;\n\t}"
        :: "r"(d_tmem), "l"(a_desc), "l"(b_desc), "r"(MMA_IDESC), "r"(en), "r"(0u)
        : "memory");
}
__device__ __forceinline__ void tmem_ld_x32(uint32_t* r, uint32_t a) {
    asm volatile("tcgen05.ld.sync.aligned.32x32b.x32.b32 "
        "{%0,%1,%2,%3,%4,%5,%6,%7,%8,%9,%10,%11,%12,%13,%14,%15,"
        "%16,%17,%18,%19,%20,%21,%22,%23,%24,%25,%26,%27,%28,%29,%30,%31}, [%32];"
        : "=r"(r[0]), "=r"(r[1]), "=r"(r[2]), "=r"(r[3]), "=r"(r[4]), "=r"(r[5]),
          "=r"(r[6]), "=r"(r[7]), "=r"(r[8]), "=r"(r[9]), "=r"(r[10]), "=r"(r[11]),
          "=r"(r[12]), "=r"(r[13]), "=r"(r[14]), "=r"(r[15]), "=r"(r[16]), "=r"(r[17]),
          "=r"(r[18]), "=r"(r[19]), "=r"(r[20]), "=r"(r[21]), "=r"(r[22]), "=r"(r[23]),
          "=r"(r[24]), "=r"(r[25]), "=r"(r[26]), "=r"(r[27]), "=r"(r[28]), "=r"(r[29]),
          "=r"(r[30]), "=r"(r[31])
        : "r"(a));
}
// 3-pass split-bf16 MMA for one 128x128x128 layer: Ah*Wh + Ah*Wl + Al*Wh
__device__ __forceinline__ void issue_mma3(uint32_t sb, uint32_t aoff, uint32_t woff,
                                           uint32_t tb_d) {
    int first = 1;
#pragma unroll
    for (int pass = 0; pass < 3; pass++) {
        uint32_t a = (pass == 2) ? aoff + 32768u : aoff;
        uint32_t w = (pass == 1) ? woff + 32768u : woff;
#pragma unroll
        for (int c = 0; c < 2; c++) {
            uint64_t ad = mkdesc(sb + a + c * 16384);
            uint64_t bd = mkdesc(sb + w + c * 16384);
#pragma unroll
            for (int ks = 0; ks < 4; ks++) {
                mma_f16_ss(tb_d, ad + ks * 2, bd + ks * 2, first ? 0u : 1u);
                first = 0;
            }
        }
    }
}
// load 128xD fp32 rows (opt relu on first, opt add second), split, store swizzled hi/lo
__device__ __forceinline__ void load_split_A(const float* __restrict__ A1,
                                             const float* __restrict__ A2, int reluFirst,
                                             int row0, int nrows, char* abase, int tid) {
#pragma unroll
    for (int q0 = 0; q0 < 16; q0++) {
        int q = tid + q0 * 256;
        int row = q >> 5, k = (q & 31) << 2;
        int gr = row0 + row;
        float4 v = make_float4(0.f, 0.f, 0.f, 0.f);
        if (gr < nrows) {
            v = *(const float4*)(A1 + (size_t)gr * D + k);
            if (reluFirst) {
                v.x = fmaxf(v.x, 0.f); v.y = fmaxf(v.y, 0.f);
                v.z = fmaxf(v.z, 0.f); v.w = fmaxf(v.w, 0.f);
            }
            if (A2) {
                float4 u = *(const float4*)(A2 + (size_t)gr * D + k);
                v.x += u.x; v.y += u.y; v.z += u.z; v.w += u.w;
            }
        }
        uint2 hi, lo;
        split4(v, hi, lo);
        int chunk = k >> 6, kin = k & 63;
        uint32_t bo = row * 128 + kin * 2;
        uint32_t sw = bo ^ ((bo >> 3) & 0x70);
        *(uint2*)(abase + chunk * 16384 + sw) = hi;
        *(uint2*)(abase + chunk * 16384 + 32768 + sw) = lo;
    }
}
// plain 64KB tile copy (global image -> smem), same layout
__device__ __forceinline__ void copy_w(const void* __restrict__ Wt, char* wbase, int tid) {
    const float4* ws = (const float4*)Wt;
    float4* wd = (float4*)wbase;
#pragma unroll
    for (int q = 0; q < 16; q++) wd[tid + q * 256] = ws[tid + q * 256];
}
// 8-warp epilogue to global: warps (w>>2) take col halves, rows = (w&3)*32+lane
__device__ __forceinline__ void ep_store_global(uint32_t tb_d, float* __restrict__ outp,
                                                int addBvec, int row0, int nrows,
                                                int wid, int lid) {
    int colb = (wid >> 2) * 64;
    int rloc = (wid & 3) * 32 + lid;
    int gr = row0 + rloc;
    uint32_t dr[64];
    tmem_ld_x32(dr, tb_d + colb);
    tmem_ld_x32(dr + 32, tb_d + colb + 32);
    asm volatile("tcgen05.wait::ld.sync.aligned;" ::: "memory");
    if (gr < nrows) {
        float4* cp = (float4*)(outp + (size_t)gr * D + colb);
#pragma unroll
        for (int j = 0; j < 16; j++) {
            float4 f = make_float4(__uint_as_float(dr[j * 4]), __uint_as_float(dr[j * 4 + 1]),
                                   __uint_as_float(dr[j * 4 + 2]), __uint_as_float(dr[j * 4 + 3]));
            if (addBvec) {
                f.x += g_vecs[6 * D + colb + j * 4];
                f.y += g_vecs[6 * D + colb + j * 4 + 1];
                f.z += g_vecs[6 * D + colb + j * 4 + 2];
                f.w += g_vecs[6 * D + colb + j * 4 + 3];
            }
            cp[j] = f;
        }
    }
    asm volatile("tcgen05.fence::before_thread_sync;" ::: "memory");
}
#endif  // HAS_TCGEN05

// ---------------- small utility kernels ----------------
__global__ void vecprep_k(const float* Wg0, const float* al0, const float* ar0,
                          const float* Wg1, const float* al1, const float* ar1,
                          const float* Wg2, const float* al2, const float* ar2,
                          const float* Wl, const float* bias,
                          const float* Wpn, const float* Wpc) {
    int k = threadIdx.x;
    float s;
    s = 0.f; for (int j = 0; j < D; j++) s += al0[j] * Wg0[j * D + k]; g_vecs[0 * D + k] = s;
    s = 0.f; for (int j = 0; j < D; j++) s += ar0[j] * Wg0[j * D + k]; g_vecs[1 * D + k] = s;
    s = 0.f; for (int j = 0; j < D; j++) s += al1[j] * Wg1[j * D + k]; g_vecs[2 * D + k] = s;
    s = 0.f; for (int j = 0; j < D; j++) s += ar1[j] * Wg1[j * D + k]; g_vecs[3 * D + k] = s;
    s = 0.f; for (int j = 0; j < D; j++) s += al2[j] * Wg2[j * D + k]; g_vecs[4 * D + k] = s;
    s = 0.f; for (int j = 0; j < D; j++) s += ar2[j] * Wg2[j * D + k]; g_vecs[5 * D + k] = s;
    s = 0.f; for (int j = 0; j < D; j++) s += Wl[(size_t)k * 2 * D + D + j] * bias[j]; g_vecs[6 * D + k] = s;
    __syncthreads();
    // x-space logit vectors: w16[r][k16] = sum_d Wp_src(r)[d][k16] * vecs[r][d]
    if (k < 16) {
#pragma unroll
        for (int r = 0; r < 6; r++) {
            const float* Wp = (r == 0 || r == 3) ? Wpc : Wpn;   // src types: cell,net,net,cell,net,net
            float acc = 0.f;
            for (int d = 0; d < D; d++) acc += Wp[d * DIN + k] * g_vecs[r * D + d];
            g_w16[r * 16 + k] = acc;
        }
    }
}

// weight prep: split fp32 into bf16 hi/lo, pre-swizzled SMEM tile images (5 weights)
__global__ void wprep_all_k(const float* __restrict__ Wl, const float* __restrict__ Wg0,
                            const float* __restrict__ Wg1, const float* __restrict__ Wg2) {
    int gid = blockIdx.x * blockDim.x + threadIdx.x;
    if (gid >= 5 * 16384) return;
    int w = gid >> 14, i = gid & 16383;
    const float* src; int ld, off;
    if (w == 0)      { src = Wl;  ld = 256; off = 0;   }
    else if (w == 1) { src = Wl;  ld = 256; off = 128; }
    else if (w == 2) { src = Wg0; ld = 128; off = 0;   }
    else if (w == 3) { src = Wg1; ld = 128; off = 0;   }
    else             { src = Wg2; ld = 128; off = 0;   }
    int j = i >> 7, k = i & 127;
    float v = src[(size_t)j * ld + off + k];
    __nv_bfloat16 h = __float2bfloat16(v);
    __nv_bfloat16 l = __float2bfloat16(v - __bfloat162float(h));
    int chunk = k >> 6;
    uint32_t bo = j * 128 + (k & 63) * 2;
    uint32_t sw = bo ^ ((bo >> 3) & 0x70);
    char* hb = (char*)g_wt + w * 65536 + chunk * 16384;
    *(__nv_bfloat16*)(hb + sw) = h;
    *(__nv_bfloat16*)(hb + 32768 + sw) = l;
}

// ---------------- fused projection + logits + zero-init: register-resident Wp ----------------
// One warp processes 32 consecutive nodes of one type. Wp columns live in registers
// (4 cols x 16 per lane); x rows broadcast via shfl. h written directly as split-bf16
// swizzled tile images. Logits computed per-lane in x-space (w16 = Wp^T @ vec).
// Net warps also zero G0/G1/G2 rows and dn0/dn1/dn2.
__global__ __launch_bounds__(256) void projlog_k(
    const float* __restrict__ xn, const float* __restrict__ xc,
    const float* __restrict__ Wpn, const float* __restrict__ Wpc, int n, int nwpt) {
    __shared__ float Ws[2][128 * 17];
    __shared__ float w16s[96];
    int tid = threadIdx.x;
    for (int i = tid; i < 2048; i += 256) {
        int d = i >> 4, k = i & 15;
        Ws[0][d * 17 + k] = Wpn[i];
        Ws[1][d * 17 + k] = Wpc[i];
    }
    for (int i = tid; i < 96; i += 256) w16s[i] = g_w16[i];
    __syncthreads();

    int gw = blockIdx.x * 8 + (tid >> 5);
    if (gw >= 2 * nwpt) return;
    int lane = tid & 31;
    int type = gw >= nwpt ? 1 : 0;
    int base = (gw - type * nwpt) * 32;

    // Wp columns 4*lane..4*lane+3 into registers (one-time smem read)
    float Wreg[4][16];
#pragma unroll
    for (int c = 0; c < 4; c++)
#pragma unroll
        for (int k = 0; k < 16; k++) Wreg[c][k] = Ws[type][(4 * lane + c) * 17 + k];

    // lane's own x row
    int mynode = base + lane;
    float x[16];
    {
        const float* xsrc = type ? xc : xn;
        if (mynode < n) {
            const float4* x4 = (const float4*)(xsrc + (size_t)mynode * DIN);
#pragma unroll
            for (int i = 0; i < 4; i++) {
                float4 v = x4[i];
                x[i * 4] = v.x; x[i * 4 + 1] = v.y; x[i * 4 + 2] = v.z; x[i * 4 + 3] = v.w;
            }
        } else {
#pragma unroll
            for (int i = 0; i < 16; i++) x[i] = 0.f;
        }
    }

    // logits for own node (x-space), plus dn zero (net warps own the node-id space)
    if (mynode < n) {
        if (type == 0) {
            float s1 = 0.f, s2 = 0.f, s4 = 0.f, s5 = 0.f;
#pragma unroll
            for (int k = 0; k < 16; k++) {
                s1 = fmaf(x[k], w16s[1 * 16 + k], s1);
                s2 = fmaf(x[k], w16s[2 * 16 + k], s2);
                s4 = fmaf(x[k], w16s[4 * 16 + k], s4);
                s5 = fmaf(x[k], w16s[5 * 16 + k], s5);
            }
            g_er0[mynode] = s1; g_el1[mynode] = s2; g_el2[mynode] = s4; g_er2[mynode] = s5;
            g_dn0[mynode] = 0.f; g_dn1[mynode] = 0.f; g_dn2[mynode] = 0.f;
        } else {
            float s0 = 0.f, s3 = 0.f;
#pragma unroll
            for (int k = 0; k < 16; k++) {
                s0 = fmaf(x[k], w16s[0 * 16 + k], s0);
                s3 = fmaf(x[k], w16s[3 * 16 + k], s3);
            }
            g_el0[mynode] = s0; g_er1[mynode] = s3;
        }
    }

    uint8_t* img = type ? g_himg_cell : g_himg_net;
    float4 z4 = make_float4(0.f, 0.f, 0.f, 0.f);
    for (int s = 0; s < 32; s++) {
        int node = base + s;
        float h[4] = {0.f, 0.f, 0.f, 0.f};
#pragma unroll
        for (int k = 0; k < 16; k++) {
            float xk = __shfl_sync(0xffffffffu, x[k], s);
            h[0] = fmaf(xk, Wreg[0][k], h[0]);
            h[1] = fmaf(xk, Wreg[1][k], h[1]);
            h[2] = fmaf(xk, Wreg[2][k], h[2]);
            h[3] = fmaf(xk, Wreg[3][k], h[3]);
        }
        // store split-bf16 into swizzled tile image (pad rows beyond n are zeros)
        uint2 hi, lo;
        split4(make_float4(h[0], h[1], h[2], h[3]), hi, lo);
        char* tb = (char*)img + (size_t)(node >> 7) * 65536;
        int chunk = lane >> 4;
        uint32_t bo = (node & 127) * 128 + ((4 * lane) & 63) * 2;
        uint32_t sw = bo ^ ((bo >> 3) & 0x70);
        *(uint2*)(tb + chunk * 16384 + sw) = hi;
        *(uint2*)(tb + chunk * 16384 + 32768 + sw) = lo;
        // zero G rows (net warps only; id space shared)
        if (type == 0 && node < n) {
            ((float4*)(g_G0 + (size_t)node * D))[lane] = z4;
            ((float4*)(g_G1 + (size_t)node * D))[lane] = z4;
            ((float4*)(g_G2 + (size_t)node * D))[lane] = z4;
        }
    }
}

// fused edge softmax numerator + denominator, all 3 relations in one launch
// (scalar footprint ~13 MB — safely L2-resident even merged)
__global__ void edge12m_k(const int* __restrict__ src0, const int* __restrict__ dst0,
                          const int* __restrict__ src1, const int* __restrict__ dst1,
                          const int* __restrict__ src2, const int* __restrict__ dst2,
                          int E0, int E1, int E2) {
    int e = blockIdx.x * blockDim.x + threadIdx.x;
    const int *src, *dst; const float *elv, *erv; float *se, *den;
    if (e < E0) {
        src = src0; dst = dst0; elv = g_el0; erv = g_er0; se = g_se0; den = g_dn0;
    } else if (e < E0 + E1) {
        e -= E0;
        src = src1; dst = dst1; elv = g_el1; erv = g_er1; se = g_se1; den = g_dn1;
    } else if (e < E0 + E1 + E2) {
        e -= E0 + E1;
        src = src2; dst = dst2; elv = g_el2; erv = g_er2; se = g_se2; den = g_dn2;
    } else return;
    float s = elv[src[e]] + erv[dst[e]];
    s = s > 0.f ? s : 0.2f * s;
    float ex = expf(s);
    se[e] = ex;
    atomicAdd(&den[dst[e]], ex);
}

// weighted scatter, ONE relation per launch: G[dst] += alpha * hsrc[src].
// One warp per edge, float4 atomics. Per-relation working set (hsrc 51MB + G 51MB
// + se/idx ~12MB) fits L2 (126MB) -> gathers hit L2, G lines stay resident.
__global__ void edge3_k(const int* __restrict__ src, const int* __restrict__ dst,
                        const float* __restrict__ se, const float* __restrict__ den,
                        const float* __restrict__ hs, float* __restrict__ G, int ne) {
    int t = blockIdx.x * blockDim.x + threadIdx.x;
    int e = t >> 5, lane = t & 31;
    if (e >= ne) return;
    int s = src[e], d = dst[e];
    float alpha = se[e] / den[d];
    float4 v = ((const float4*)(hs + (size_t)s * D))[lane];
    v.x *= alpha; v.y *= alpha; v.z *= alpha; v.w *= alpha;
    atomicAdd(((float4*)(G + (size_t)d * D)) + lane, v);
}

// ---------------- fused 5-GEMM kernel (c_net, hs1, hs2, c_cell, hs0) ----------------
// smem: [0] tmem ptr, [8],[16] mbarriers, A_net hi/lo 64KB, A_cell hi/lo 64KB, W 64KB
#define SM_A0 1024
#define SM_A1 (1024 + 65536)
#define SM_W5 (1024 + 131072)
#define SM5_TOTAL (1024 + 196608)

__global__ __launch_bounds__(256, 1) void gemm5_k(int nrows) {
#if HAS_TCGEN05
    extern __shared__ char smem[];
    uint32_t sb = smem_u32(smem);
    int tid = threadIdx.x, wid = tid >> 5, lid = tid & 31;
    int row0 = blockIdx.x * 128;

    if (tid == 0) {
        asm volatile("mbarrier.init.shared.b64 [%0], 1;" :: "r"(sb + 8) : "memory");
        asm volatile("mbarrier.init.shared.b64 [%0], 1;" :: "r"(sb + 16) : "memory");
    }
    if (wid == 0)
        asm volatile("tcgen05.alloc.cta_group::1.sync.aligned.shared::cta.b32 [%0], %1;"
                     :: "r"(sb), "r"(512u) : "memory");
    __syncthreads();
    uint32_t tb = *(volatile uint32_t*)smem;

    // A tiles arrive pre-split/pre-swizzled from projlog — plain 64KB copies
    copy_w(g_himg_net  + (size_t)blockIdx.x * 65536, smem + SM_A0, tid);
    copy_w(g_himg_cell + (size_t)blockIdx.x * 65536, smem + SM_A1, tid);
    copy_w(g_wt + 0 * 32768, smem + SM_W5, tid);   // W for layer 0 (Wla)
    asm volatile("fence.proxy.async.shared::cta;" ::: "memory");
    __syncthreads();

    const uint32_t aoff[5] = {SM_A0, SM_A0, SM_A0, SM_A1, SM_A1};
    const int wsel[5] = {0, 3, 4, 0, 2};
    float* const outp[5] = {g_c_net, g_hsrc1, g_hsrc2, g_c_cell, g_hsrc0};
    const int bvf[5] = {1, 0, 0, 1, 0};
    const uint32_t par[5] = {0, 0, 1, 1, 0};

#pragma unroll
    for (int i = 0; i < 5; i++) {
        asm volatile("tcgen05.fence::after_thread_sync;" ::: "memory");
        if (wid == 0 && elect1()) {
            issue_mma3(sb, aoff[i], SM_W5, tb + (i & 1) * 128);
            asm volatile(
                "tcgen05.commit.cta_group::1.mbarrier::arrive::one.shared::cluster.b64 [%0];"
                :: "r"(sb + 8 + (i & 1) * 8) : "memory");
        }
        if (i > 0)   // epilogue of previous layer overlaps this layer's MMA
            ep_store_global(tb + ((i - 1) & 1) * 128, outp[i - 1], bvf[i - 1],
                            row0, nrows, wid, lid);
        mbar_waitp(sb + 8 + (i & 1) * 8, par[i]);   // MMA_i done (W safe to overwrite)
        if (i < 4) {
            copy_w(g_wt + wsel[i + 1] * 32768, smem + SM_W5, tid);
            asm volatile("fence.proxy.async.shared::cta;" ::: "memory");
            __syncthreads();
        }
    }
    asm volatile("tcgen05.fence::after_thread_sync;" ::: "memory");
    ep_store_global(tb + 0, outp[4], bvf[4], row0, nrows, wid, lid);

    __syncthreads();
    if (wid == 0) {
        asm volatile("tcgen05.relinquish_alloc_permit.cta_group::1.sync.aligned;");
        asm volatile("tcgen05.dealloc.cta_group::1.sync.aligned.b32 %0, %1;" :: "r"(tb), "r"(512u));
    }
#endif
}

// ---------------- fused F-chain kernel ----------------
// net CTAs (blockIdx < gbn):  out_net = relu(C+ (relu(C+ relu(C+G0@W)@W) + G2)@W)
// cell CTAs: out_cell = relu(C + relu(C + (relu(C)+G1)@W)@W)      (C includes bvec)
// smem: A hi/lo 64KB, W (Wlb) 64KB, C fp32 tile padded stride 129 (66048 B)
#define SMC_A 1024
#define SMC_W (1024 + 65536)
#define SMC_C (1024 + 131072)
#define SMC_TOTAL (1024 + 131072 + 66048)

__global__ __launch_bounds__(256, 1) void chain_k(float* __restrict__ out, int nrows, int gbn) {
#if HAS_TCGEN05
    extern __shared__ char smem[];
    uint32_t sb = smem_u32(smem);
    int tid = threadIdx.x, wid = tid >> 5, lid = tid & 31;
    int isNet = blockIdx.x < gbn;
    int row0 = (isNet ? blockIdx.x : blockIdx.x - gbn) * 128;

    if (tid == 0)
        asm volatile("mbarrier.init.shared.b64 [%0], 1;" :: "r"(sb + 8) : "memory");
    if (wid == 0)
        asm volatile("tcgen05.alloc.cta_group::1.sync.aligned.shared::cta.b32 [%0], %1;"
                     :: "r"(sb), "r"(512u) : "memory");
    __syncthreads();
    uint32_t tb = *(volatile uint32_t*)smem;

    const float* Cg = isNet ? g_c_net : g_c_cell;
    float* Cs = (float*)(smem + SMC_C);
    // C tile into smem, padded stride 129 floats (conflict-free scalar reads)
#pragma unroll
    for (int q0 = 0; q0 < 16; q0++) {
        int q = tid + q0 * 256;
        int row = q >> 5, k = (q & 31) << 2;
        int gr = row0 + row;
        float4 v = make_float4(0.f, 0.f, 0.f, 0.f);
        if (gr < nrows) v = *(const float4*)(Cg + (size_t)gr * D + k);
        Cs[row * 129 + k] = v.x; Cs[row * 129 + k + 1] = v.y;
        Cs[row * 129 + k + 2] = v.z; Cs[row * 129 + k + 3] = v.w;
    }
    // first A:  net -> G0 ; cell -> relu(C)+G1
    if (isNet) load_split_A(g_G0, nullptr, 0, row0, nrows, smem + SMC_A, tid);
    else       load_split_A(g_c_cell, g_G1, 1, row0, nrows, smem + SMC_A, tid);
    copy_w(g_wt + 1 * 32768, smem + SMC_W, tid);   // Wlb
    asm volatile("fence.proxy.async.shared::cta;" ::: "memory");
    __syncthreads();

    int nl = isNet ? 3 : 2;
    int colb = (wid >> 2) * 64;
    int rloc = (wid & 3) * 32 + lid;
    int gr = row0 + rloc;

    for (int l = 0; l < nl; l++) {
        asm volatile("tcgen05.fence::after_thread_sync;" ::: "memory");
        if (wid == 0 && elect1()) {
            issue_mma3(sb, SMC_A, SMC_W, tb);
            asm volatile(
                "tcgen05.commit.cta_group::1.mbarrier::arrive::one.shared::cluster.b64 [%0];"
                :: "r"(sb + 8) : "memory");
        }
        mbar_waitp(sb + 8, (uint32_t)(l & 1));
        asm volatile("tcgen05.fence::after_thread_sync;" ::: "memory");

        uint32_t dr[64];
        tmem_ld_x32(dr, tb + colb);
        tmem_ld_x32(dr + 32, tb + colb + 32);
        asm volatile("tcgen05.wait::ld.sync.aligned;" ::: "memory");

        float o[64];
#pragma unroll
        for (int j = 0; j < 64; j++) {
            float v = __uint_as_float(dr[j]) + Cs[rloc * 129 + colb + j];
            o[j] = v > 0.f ? v : 0.f;
        }
        if (l == nl - 1) {
            if (gr < nrows) {
                float4* dp = (float4*)(out + (size_t)(isNet ? gr : nrows + gr) * D + colb);
#pragma unroll
                for (int j = 0; j < 16; j++)
                    dp[j] = make_float4(o[j * 4], o[j * 4 + 1], o[j * 4 + 2], o[j * 4 + 3]);
            }
            asm volatile("tcgen05.fence::before_thread_sync;" ::: "memory");
        } else {
            if (isNet && l == 1 && gr < nrows) {   // add G2 before final layer
                const float4* g2 = (const float4*)(g_G2 + (size_t)gr * D + colb);
#pragma unroll
                for (int j = 0; j < 16; j++) {
                    float4 u = g2[j];
                    o[j * 4] += u.x; o[j * 4 + 1] += u.y; o[j * 4 + 2] += u.z; o[j * 4 + 3] += u.w;
                }
            }
            // re-split into A smem (rows beyond nrows are exact zeros: acc=0, C=0)
#pragma unroll
            for (int j = 0; j < 16; j++) {
                float4 v = make_float4(o[j * 4], o[j * 4 + 1], o[j * 4 + 2], o[j * 4 + 3]);
                uint2 hi, lo;
                split4(v, hi, lo);
                int chunk = colb >> 6;
                uint32_t bo = rloc * 128 + (j * 4) * 2;
                uint32_t sw = bo ^ ((bo >> 3) & 0x70);
                *(uint2*)(smem + SMC_A + chunk * 16384 + sw) = hi;
                *(uint2*)(smem + SMC_A + chunk * 16384 + 32768 + sw) = lo;
            }
            asm volatile("fence.proxy.async.shared::cta;" ::: "memory");
            asm volatile("tcgen05.fence::before_thread_sync;" ::: "memory");
            __syncthreads();
        }
    }

    __syncthreads();
    if (wid == 0) {
        asm volatile("tcgen05.relinquish_alloc_permit.cta_group::1.sync.aligned;");
        asm volatile("tcgen05.dealloc.cta_group::1.sync.aligned.b32 %0, %1;" :: "r"(tb), "r"(512u));
    }
#endif
}

// ---------------- host launch ----------------
extern "C" void kernel_launch(void* const* d_in, const int* in_sizes, int n_in,
                              void* d_out, int out_size) {
    const float* x_net   = (const float*)d_in[0];
    const float* x_cell  = (const float*)d_in[1];
    const float* Wp_net  = (const float*)d_in[2];
    const float* Wp_cell = (const float*)d_in[3];
    const float* Wg0 = (const float*)d_in[4];
    const float* al0 = (const float*)d_in[5];
    const float* ar0 = (const float*)d_in[6];
    const float* Wg1 = (const float*)d_in[7];
    const float* al1 = (const float*)d_in[8];
    const float* ar1 = (const float*)d_in[9];
    const float* Wg2 = (const float*)d_in[10];
    const float* al2 = (const float*)d_in[11];
    const float* ar2 = (const float*)d_in[12];
    const float* Wl   = (const float*)d_in[13];
    const float* bias = (const float*)d_in[14];
    const int* src0 = (const int*)d_in[15];
    const int* dst0 = (const int*)d_in[16];
    const int* src1 = (const int*)d_in[17];
    const int* dst1 = (const int*)d_in[18];
    const int* src2 = (const int*)d_in[19];
    const int* dst2 = (const int*)d_in[20];

    int n  = in_sizes[0] / DIN;
    int E0 = in_sizes[15], E1 = in_sizes[17], E2 = in_sizes[19];
    float* out = (float*)d_out;
    int gb = (n + 127) / 128;
    int nwpt = gb * 4;           // warps per node type (covers full tile padding)
    int Et = E0 + E1 + E2;

    float *se0, *se1, *se2, *dn0, *dn1, *dn2, *hs0, *hs1, *hs2, *G0, *G1, *G2;
    cudaGetSymbolAddress((void**)&se0, g_se0);
    cudaGetSymbolAddress((void**)&se1, g_se1);
    cudaGetSymbolAddress((void**)&se2, g_se2);
    cudaGetSymbolAddress((void**)&dn0, g_dn0);
    cudaGetSymbolAddress((void**)&dn1, g_dn1);
    cudaGetSymbolAddress((void**)&dn2, g_dn2);
    cudaGetSymbolAddress((void**)&hs0, g_hsrc0);
    cudaGetSymbolAddress((void**)&hs1, g_hsrc1);
    cudaGetSymbolAddress((void**)&hs2, g_hsrc2);
    cudaGetSymbolAddress((void**)&G0, g_G0);
    cudaGetSymbolAddress((void**)&G1, g_G1);
    cudaGetSymbolAddress((void**)&G2, g_G2);

    cudaFuncSetAttribute(gemm5_k, cudaFuncAttributeMaxDynamicSharedMemorySize, SM5_TOTAL);
    cudaFuncSetAttribute(chain_k, cudaFuncAttributeMaxDynamicSharedMemorySize, SMC_TOTAL);

    vecprep_k<<<1, 128>>>(Wg0, al0, ar0, Wg1, al1, ar1, Wg2, al2, ar2, Wl, bias,
                          Wp_net, Wp_cell);                                             // 1
    wprep_all_k<<<(5 * 16384 + 255) / 256, 256>>>(Wl, Wg0, Wg1, Wg2);                   // 2
    projlog_k<<<(2 * nwpt + 7) / 8, 256>>>(x_net, x_cell, Wp_net, Wp_cell, n, nwpt);    // 3
    gemm5_k<<<gb, 256, SM5_TOTAL>>>(n);                                                 // 4
    edge12m_k<<<(Et + 255) / 256, 256>>>(src0, dst0, src1, dst1, src2, dst2,
                                         E0, E1, E2);                                   // 5
    // per-relation scatters: hs0 first (freshest in L2 from gemm5's last layer)
    edge3_k<<<(E0 * 32 + 255) / 256, 256>>>(src0, dst0, se0, dn0, hs0, G0, E0);         // 6
    edge3_k<<<(E1 * 32 + 255) / 256, 256>>>(src1, dst1, se1, dn1, hs1, G1, E1);         // 7
    edge3_k<<<(E2 * 32 + 255) / 256, 256>>>(src2, dst2, se2, dn2, hs2, G2, E2);         // 8
    chain_k<<<2 * gb, 256, SMC_TOTAL>>>(out, n, gb);                                    // 9
}

// round 17
// speedup vs baseline: 1.2613x; 1.0175x over previous
#include <cuda_runtime.h>
#include <cuda_bf16.h>
#include <math.h>
#include <stdint.h>

#define D 128
#define DIN 16
#define NMAX 100000
#define EMAX 600000
#define NTILES 782   // ceil(NMAX/128)

// tcgen05 is an arch-accelerated ("a") feature: only emit it in passes that
// target sm_103a / sm_100a. The plain compute_103 PTX fallback pass gets an
// empty body (never executed at runtime — the sm_103a cubin is used).
#if defined(__CUDA_ARCH_FEAT_SM103_ALL) || defined(__CUDA_ARCH_FEAT_SM100_ALL) || defined(__CUDA_ARCH_FEAT_SM101_ALL)
#define HAS_TCGEN05 1
#else
#define HAS_TCGEN05 0
#endif

// ---------------- scratch (static device globals; no allocations) ----------------
// h stored ONLY as pre-swizzled bf16 hi/lo 64KB tile images (GEMM SMEM format)
__device__ uint8_t g_himg_net [(size_t)NTILES * 65536];
__device__ uint8_t g_himg_cell[(size_t)NTILES * 65536];
__device__ float g_c_net [(size_t)NMAX * D];   // feat@Wla^T + bvec  (net)
__device__ float g_c_cell[(size_t)NMAX * D];   // feat@Wla^T + bvec  (cell)
__device__ float g_hsrc0 [(size_t)NMAX * D];   // h_cell@Wg0^T
__device__ float g_hsrc1 [(size_t)NMAX * D];   // h_net @Wg1^T
__device__ float g_hsrc2 [(size_t)NMAX * D];   // h_net @Wg2^T
__device__ float g_G0    [(size_t)NMAX * D];
__device__ float g_G1    [(size_t)NMAX * D];
__device__ float g_G2    [(size_t)NMAX * D];
__device__ float g_se0[EMAX], g_se1[EMAX], g_se2[EMAX];
__device__ float g_dn0[NMAX], g_dn1[NMAX], g_dn2[NMAX];
__device__ float g_el0[NMAX], g_er0[NMAX], g_el1[NMAX], g_er1[NMAX], g_el2[NMAX], g_er2[NMAX];
// vecs rows: 0 wl0(cell) 1 wr0(net) 2 wl1(net) 3 wr1(cell) 4 wl2(net) 5 wr2(net) 6 bvec
__device__ float g_vecs[7 * D];
// x-space logit vectors: w16[r] = Wp_srctype(r)^T @ vecs[r]   (6 x 16)
__device__ float g_w16[6 * 16];
// pre-swizzled bf16 hi/lo weight tiles: idx 0=Wla 1=Wlb 2=Wg0 3=Wg1 4=Wg2 (32768 bf16 each)
__device__ __nv_bfloat16 g_wt[5 * 32768];

// ---------------- helpers ----------------
__device__ __forceinline__ uint32_t smem_u32(const void* p) {
    uint32_t r;
    asm("{ .reg .u64 t; cvta.to.shared.u64 t, %1; cvt.u32.u64 %0, t; }" : "=r"(r) : "l"(p));
    return r;
}
__device__ __forceinline__ uint32_t elect1() {
    uint32_t p;
    asm volatile("{\n\t.reg .pred p;\n\telect.sync _|p, 0xFFFFFFFF;\n\tselp.b32 %0, 1, 0, p;\n\t}" : "=r"(p));
    return p;
}
// SW128 K-major descriptor: layout=2, version=1, SBO=64, LBO=1
__device__ __forceinline__ uint64_t mkdesc(uint32_t addr) {
    return ((uint64_t)2 << 61) | ((uint64_t)1 << 46) | ((uint64_t)64 << 32) |
           ((uint64_t)1 << 16) | ((uint64_t)(addr >> 4) & 0x3FFF);
}
// idesc kind::f16: dtype=F32, atype=btype=BF16, N=128, M=128
#define MMA_IDESC 0x08200490u

__device__ __forceinline__ void mbar_waitp(uint32_t mbar, uint32_t parity) {
    asm volatile(
        "{\n\t.reg .pred P1;\n\t"
        "WAIT_LOOP_%=:\n\t"
        "mbarrier.try_wait.parity.acquire.cta.shared::cta.b64 P1, [%0], %1, 0x989680;\n\t"
        "@P1 bra.uni WAIT_DONE_%=;\n\t"
        "bra.uni WAIT_LOOP_%=;\n\t"
        "WAIT_DONE_%=:\n\t}"
        :: "r"(mbar), "r"(parity) : "memory");
}
// async bulk copy global->shared with mbarrier tx-completion
__device__ __forceinline__ void bulk_cp(uint32_t dst, const void* src, uint32_t bytes,
                                        uint32_t mbar) {
    asm volatile("mbarrier.arrive.expect_tx.shared.b64 _, [%0], %1;"
                 :: "r"(mbar), "r"(bytes) : "memory");
    asm volatile("cp.async.bulk.shared::cta.global.mbarrier::complete_tx::bytes "
                 "[%0], [%1], %2, [%3];"
                 :: "r"(dst), "l"(src), "r"(bytes), "r"(mbar) : "memory");
}

__device__ __forceinline__ uint32_t pk2(float a, float b) {
    uint16_t ha = __bfloat16_as_ushort(__float2bfloat16(a));
    uint16_t hb = __bfloat16_as_ushort(__float2bfloat16(b));
    return (uint32_t)ha | ((uint32_t)hb << 16);
}
__device__ __forceinline__ void split4(float4 v, uint2& hi, uint2& lo) {
    __nv_bfloat16 h0 = __float2bfloat16(v.x), h1 = __float2bfloat16(v.y);
    __nv_bfloat16 h2 = __float2bfloat16(v.z), h3 = __float2bfloat16(v.w);
    hi.x = (uint32_t)__bfloat16_as_ushort(h0) | ((uint32_t)__bfloat16_as_ushort(h1) << 16);
    hi.y = (uint32_t)__bfloat16_as_ushort(h2) | ((uint32_t)__bfloat16_as_ushort(h3) << 16);
    lo.x = pk2(v.x - __bfloat162float(h0), v.y - __bfloat162float(h1));
    lo.y = pk2(v.z - __bfloat162float(h2), v.w - __bfloat162float(h3));
}

#if HAS_TCGEN05
__device__ __forceinline__ void mma_f16_ss(uint32_t d_tmem, uint64_t a_desc, uint64_t b_desc,
                                           uint32_t en) {
    asm volatile(
        "{\n\t.reg .pred p;\n\tsetp.ne.u32 p, %4, 0;\n\t"
        "tcgen05.mma.cta_group::1.kind::f16 [%0], %1, %2, %3, {%5, %5, %5, %5}, p;\n\t}"
        :: "r"(d_tmem), "l"(a_desc), "l"(b_desc), "r"(MMA_IDESC), "r"(en), "r"(0u)
        : "memory");
}
__device__ __forceinline__ void tmem_ld_x32(uint32_t* r, uint32_t a) {
    asm volatile("tcgen05.ld.sync.aligned.32x32b.x32.b32 "
        "{%0,%1,%2,%3,%4,%5,%6,%7,%8,%9,%10,%11,%12,%13,%14,%15,"
        "%16,%17,%18,%19,%20,%21,%22,%23,%24,%25,%26,%27,%28,%29,%30,%31}, [%32];"
        : "=r"(r[0]), "=r"(r[1]), "=r"(r[2]), "=r"(r[3]), "=r"(r[4]), "=r"(r[5]),
          "=r"(r[6]), "=r"(r[7]), "=r"(r[8]), "=r"(r[9]), "=r"(r[10]), "=r"(r[11]),
          "=r"(r[12]), "=r"(r[13]), "=r"(r[14]), "=r"(r[15]), "=r"(r[16]), "=r"(r[17]),
          "=r"(r[18]), "=r"(r[19]), "=r"(r[20]), "=r"(r[21]), "=r"(r[22]), "=r"(r[23]),
          "=r"(r[24]), "=r"(r[25]), "=r"(r[26]), "=r"(r[27]), "=r"(r[28]), "=r"(r[29]),
          "=r"(r[30]), "=r"(r[31])
        : "r"(a));
}
// 3-pass split-bf16 MMA for one 128x128x128 layer: Ah*Wh + Ah*Wl + Al*Wh
__device__ __forceinline__ void issue_mma3(uint32_t sb, uint32_t aoff, uint32_t woff,
                                           uint32_t tb_d) {
    int first = 1;
#pragma unroll
    for (int pass = 0; pass < 3; pass++) {
        uint32_t a = (pass == 2) ? aoff + 32768u : aoff;
        uint32_t w = (pass == 1) ? woff + 32768u : woff;
#pragma unroll
        for (int c = 0; c < 2; c++) {
            uint64_t ad = mkdesc(sb + a + c * 16384);
            uint64_t bd = mkdesc(sb + w + c * 16384);
#pragma unroll
            for (int ks = 0; ks < 4; ks++) {
                mma_f16_ss(tb_d, ad + ks * 2, bd + ks * 2, first ? 0u : 1u);
                first = 0;
            }
        }
    }
}
// load 128xD fp32 rows (opt relu on first, opt add second), split, store swizzled hi/lo
__device__ __forceinline__ void load_split_A(const float* __restrict__ A1,
                                             const float* __restrict__ A2, int reluFirst,
                                             int row0, int nrows, char* abase, int tid) {
#pragma unroll
    for (int q0 = 0; q0 < 16; q0++) {
        int q = tid + q0 * 256;
        int row = q >> 5, k = (q & 31) << 2;
        int gr = row0 + row;
        float4 v = make_float4(0.f, 0.f, 0.f, 0.f);
        if (gr < nrows) {
            v = *(const float4*)(A1 + (size_t)gr * D + k);
            if (reluFirst) {
                v.x = fmaxf(v.x, 0.f); v.y = fmaxf(v.y, 0.f);
                v.z = fmaxf(v.z, 0.f); v.w = fmaxf(v.w, 0.f);
            }
            if (A2) {
                float4 u = *(const float4*)(A2 + (size_t)gr * D + k);
                v.x += u.x; v.y += u.y; v.z += u.z; v.w += u.w;
            }
        }
        uint2 hi, lo;
        split4(v, hi, lo);
        int chunk = k >> 6, kin = k & 63;
        uint32_t bo = row * 128 + kin * 2;
        uint32_t sw = bo ^ ((bo >> 3) & 0x70);
        *(uint2*)(abase + chunk * 16384 + sw) = hi;
        *(uint2*)(abase + chunk * 16384 + 32768 + sw) = lo;
    }
}
// plain 64KB tile copy (global image -> smem), same layout
__device__ __forceinline__ void copy_w(const void* __restrict__ Wt, char* wbase, int tid) {
    const float4* ws = (const float4*)Wt;
    float4* wd = (float4*)wbase;
#pragma unroll
    for (int q = 0; q < 16; q++) wd[tid + q * 256] = ws[tid + q * 256];
}
// 8-warp epilogue to global: warps (w>>2) take col halves, rows = (w&3)*32+lane
__device__ __forceinline__ void ep_store_global(uint32_t tb_d, float* __restrict__ outp,
                                                int addBvec, int row0, int nrows,
                                                int wid, int lid) {
    int colb = (wid >> 2) * 64;
    int rloc = (wid & 3) * 32 + lid;
    int gr = row0 + rloc;
    uint32_t dr[64];
    tmem_ld_x32(dr, tb_d + colb);
    tmem_ld_x32(dr + 32, tb_d + colb + 32);
    asm volatile("tcgen05.wait::ld.sync.aligned;" ::: "memory");
    if (gr < nrows) {
        float4* cp = (float4*)(outp + (size_t)gr * D + colb);
#pragma unroll
        for (int j = 0; j < 16; j++) {
            float4 f = make_float4(__uint_as_float(dr[j * 4]), __uint_as_float(dr[j * 4 + 1]),
                                   __uint_as_float(dr[j * 4 + 2]), __uint_as_float(dr[j * 4 + 3]));
            if (addBvec) {
                f.x += g_vecs[6 * D + colb + j * 4];
                f.y += g_vecs[6 * D + colb + j * 4 + 1];
                f.z += g_vecs[6 * D + colb + j * 4 + 2];
                f.w += g_vecs[6 * D + colb + j * 4 + 3];
            }
            cp[j] = f;
        }
    }
    asm volatile("tcgen05.fence::before_thread_sync;" ::: "memory");
}
#endif  // HAS_TCGEN05

// ---------------- small utility kernels ----------------
__global__ void vecprep_k(const float* Wg0, const float* al0, const float* ar0,
                          const float* Wg1, const float* al1, const float* ar1,
                          const float* Wg2, const float* al2, const float* ar2,
                          const float* Wl, const float* bias,
                          const float* Wpn, const float* Wpc) {
    int k = threadIdx.x;
    float s;
    s = 0.f; for (int j = 0; j < D; j++) s += al0[j] * Wg0[j * D + k]; g_vecs[0 * D + k] = s;
    s = 0.f; for (int j = 0; j < D; j++) s += ar0[j] * Wg0[j * D + k]; g_vecs[1 * D + k] = s;
    s = 0.f; for (int j = 0; j < D; j++) s += al1[j] * Wg1[j * D + k]; g_vecs[2 * D + k] = s;
    s = 0.f; for (int j = 0; j < D; j++) s += ar1[j] * Wg1[j * D + k]; g_vecs[3 * D + k] = s;
    s = 0.f; for (int j = 0; j < D; j++) s += al2[j] * Wg2[j * D + k]; g_vecs[4 * D + k] = s;
    s = 0.f; for (int j = 0; j < D; j++) s += ar2[j] * Wg2[j * D + k]; g_vecs[5 * D + k] = s;
    s = 0.f; for (int j = 0; j < D; j++) s += Wl[(size_t)k * 2 * D + D + j] * bias[j]; g_vecs[6 * D + k] = s;
    __syncthreads();
    // x-space logit vectors: w16[r][k16] = sum_d Wp_src(r)[d][k16] * vecs[r][d]
    if (k < 16) {
#pragma unroll
        for (int r = 0; r < 6; r++) {
            const float* Wp = (r == 0 || r == 3) ? Wpc : Wpn;   // src types: cell,net,net,cell,net,net
            float acc = 0.f;
            for (int d = 0; d < D; d++) acc += Wp[d * DIN + k] * g_vecs[r * D + d];
            g_w16[r * 16 + k] = acc;
        }
    }
}

// weight prep: split fp32 into bf16 hi/lo, pre-swizzled SMEM tile images (5 weights)
__global__ void wprep_all_k(const float* __restrict__ Wl, const float* __restrict__ Wg0,
                            const float* __restrict__ Wg1, const float* __restrict__ Wg2) {
    int gid = blockIdx.x * blockDim.x + threadIdx.x;
    if (gid >= 5 * 16384) return;
    int w = gid >> 14, i = gid & 16383;
    const float* src; int ld, off;
    if (w == 0)      { src = Wl;  ld = 256; off = 0;   }
    else if (w == 1) { src = Wl;  ld = 256; off = 128; }
    else if (w == 2) { src = Wg0; ld = 128; off = 0;   }
    else if (w == 3) { src = Wg1; ld = 128; off = 0;   }
    else             { src = Wg2; ld = 128; off = 0;   }
    int j = i >> 7, k = i & 127;
    float v = src[(size_t)j * ld + off + k];
    __nv_bfloat16 h = __float2bfloat16(v);
    __nv_bfloat16 l = __float2bfloat16(v - __bfloat162float(h));
    int chunk = k >> 6;
    uint32_t bo = j * 128 + (k & 63) * 2;
    uint32_t sw = bo ^ ((bo >> 3) & 0x70);
    char* hb = (char*)g_wt + w * 65536 + chunk * 16384;
    *(__nv_bfloat16*)(hb + sw) = h;
    *(__nv_bfloat16*)(hb + 32768 + sw) = l;
}

// ---------------- fused projection + logits + zero-init: register-resident Wp ----------------
__global__ __launch_bounds__(256) void projlog_k(
    const float* __restrict__ xn, const float* __restrict__ xc,
    const float* __restrict__ Wpn, const float* __restrict__ Wpc, int n, int nwpt) {
    __shared__ float Ws[2][128 * 17];
    __shared__ float w16s[96];
    int tid = threadIdx.x;
    for (int i = tid; i < 2048; i += 256) {
        int d = i >> 4, k = i & 15;
        Ws[0][d * 17 + k] = Wpn[i];
        Ws[1][d * 17 + k] = Wpc[i];
    }
    for (int i = tid; i < 96; i += 256) w16s[i] = g_w16[i];
    __syncthreads();

    int gw = blockIdx.x * 8 + (tid >> 5);
    if (gw >= 2 * nwpt) return;
    int lane = tid & 31;
    int type = gw >= nwpt ? 1 : 0;
    int base = (gw - type * nwpt) * 32;

    float Wreg[4][16];
#pragma unroll
    for (int c = 0; c < 4; c++)
#pragma unroll
        for (int k = 0; k < 16; k++) Wreg[c][k] = Ws[type][(4 * lane + c) * 17 + k];

    int mynode = base + lane;
    float x[16];
    {
        const float* xsrc = type ? xc : xn;
        if (mynode < n) {
            const float4* x4 = (const float4*)(xsrc + (size_t)mynode * DIN);
#pragma unroll
            for (int i = 0; i < 4; i++) {
                float4 v = x4[i];
                x[i * 4] = v.x; x[i * 4 + 1] = v.y; x[i * 4 + 2] = v.z; x[i * 4 + 3] = v.w;
            }
        } else {
#pragma unroll
            for (int i = 0; i < 16; i++) x[i] = 0.f;
        }
    }

    if (mynode < n) {
        if (type == 0) {
            float s1 = 0.f, s2 = 0.f, s4 = 0.f, s5 = 0.f;
#pragma unroll
            for (int k = 0; k < 16; k++) {
                s1 = fmaf(x[k], w16s[1 * 16 + k], s1);
                s2 = fmaf(x[k], w16s[2 * 16 + k], s2);
                s4 = fmaf(x[k], w16s[4 * 16 + k], s4);
                s5 = fmaf(x[k], w16s[5 * 16 + k], s5);
            }
            g_er0[mynode] = s1; g_el1[mynode] = s2; g_el2[mynode] = s4; g_er2[mynode] = s5;
            g_dn0[mynode] = 0.f; g_dn1[mynode] = 0.f; g_dn2[mynode] = 0.f;
        } else {
            float s0 = 0.f, s3 = 0.f;
#pragma unroll
            for (int k = 0; k < 16; k++) {
                s0 = fmaf(x[k], w16s[0 * 16 + k], s0);
                s3 = fmaf(x[k], w16s[3 * 16 + k], s3);
            }
            g_el0[mynode] = s0; g_er1[mynode] = s3;
        }
    }

    uint8_t* img = type ? g_himg_cell : g_himg_net;
    float4 z4 = make_float4(0.f, 0.f, 0.f, 0.f);
    for (int s = 0; s < 32; s++) {
        int node = base + s;
        float h[4] = {0.f, 0.f, 0.f, 0.f};
#pragma unroll
        for (int k = 0; k < 16; k++) {
            float xk = __shfl_sync(0xffffffffu, x[k], s);
            h[0] = fmaf(xk, Wreg[0][k], h[0]);
            h[1] = fmaf(xk, Wreg[1][k], h[1]);
            h[2] = fmaf(xk, Wreg[2][k], h[2]);
            h[3] = fmaf(xk, Wreg[3][k], h[3]);
        }
        uint2 hi, lo;
        split4(make_float4(h[0], h[1], h[2], h[3]), hi, lo);
        char* tb = (char*)img + (size_t)(node >> 7) * 65536;
        int chunk = lane >> 4;
        uint32_t bo = (node & 127) * 128 + ((4 * lane) & 63) * 2;
        uint32_t sw = bo ^ ((bo >> 3) & 0x70);
        *(uint2*)(tb + chunk * 16384 + sw) = hi;
        *(uint2*)(tb + chunk * 16384 + 32768 + sw) = lo;
        if (type == 0 && node < n) {
            ((float4*)(g_G0 + (size_t)node * D))[lane] = z4;
            ((float4*)(g_G1 + (size_t)node * D))[lane] = z4;
            ((float4*)(g_G2 + (size_t)node * D))[lane] = z4;
        }
    }
}

// fused edge softmax numerator + denominator, all 3 relations in one launch
// (scalar footprint ~13 MB — safely L2-resident even merged)
__global__ void edge12m_k(const int* __restrict__ src0, const int* __restrict__ dst0,
                          const int* __restrict__ src1, const int* __restrict__ dst1,
                          const int* __restrict__ src2, const int* __restrict__ dst2,
                          int E0, int E1, int E2) {
    int e = blockIdx.x * blockDim.x + threadIdx.x;
    const int *src, *dst; const float *elv, *erv; float *se, *den;
    if (e < E0) {
        src = src0; dst = dst0; elv = g_el0; erv = g_er0; se = g_se0; den = g_dn0;
    } else if (e < E0 + E1) {
        e -= E0;
        src = src1; dst = dst1; elv = g_el1; erv = g_er1; se = g_se1; den = g_dn1;
    } else if (e < E0 + E1 + E2) {
        e -= E0 + E1;
        src = src2; dst = dst2; elv = g_el2; erv = g_er2; se = g_se2; den = g_dn2;
    } else return;
    float s = elv[src[e]] + erv[dst[e]];
    s = s > 0.f ? s : 0.2f * s;
    float ex = expf(s);
    se[e] = ex;
    atomicAdd(&den[dst[e]], ex);
}

// weighted scatter, ONE relation per launch: G[dst] += alpha * hsrc[src].
// One warp per edge, float4 atomics. Per-relation working set fits L2.
__global__ void edge3_k(const int* __restrict__ src, const int* __restrict__ dst,
                        const float* __restrict__ se, const float* __restrict__ den,
                        const float* __restrict__ hs, float* __restrict__ G, int ne) {
    int t = blockIdx.x * blockDim.x + threadIdx.x;
    int e = t >> 5, lane = t & 31;
    if (e >= ne) return;
    int s = src[e], d = dst[e];
    float alpha = se[e] / den[d];
    float4 v = ((const float4*)(hs + (size_t)s * D))[lane];
    v.x *= alpha; v.y *= alpha; v.z *= alpha; v.w *= alpha;
    atomicAdd(((float4*)(G + (size_t)d * D)) + lane, v);
}

// ---------------- async multi-layer GEMM (2 or 3 layers off one A image) ----------------
// smem: [0] tmem ptr, [8],[16] mb_mma ping-pong, [24..56] mb_cp[4],
//       A 64KB @1024, W double buffer 2x64KB.
// All smem fills via cp.async.bulk; W_{i+2} prefetch overlaps MMA_i/epilogue.
#define SG_A  1024
#define SG_W0 (1024 + 65536)
#define SG_TOTAL (1024 + 196608)

__global__ __launch_bounds__(256, 1) void gemm35_k(
    const uint8_t* __restrict__ Aimg, int nl,
    int wi0, int wi1, int wi2,
    float* o0, float* o1, float* o2, int bvmask, int nrows) {
#if HAS_TCGEN05
    extern __shared__ char smem[];
    uint32_t sb = smem_u32(smem);
    int tid = threadIdx.x, wid = tid >> 5, lid = tid & 31;
    int row0 = blockIdx.x * 128;

    if (tid == 0) {
        asm volatile("mbarrier.init.shared.b64 [%0], 1;" :: "r"(sb + 8) : "memory");
        asm volatile("mbarrier.init.shared.b64 [%0], 1;" :: "r"(sb + 16) : "memory");
#pragma unroll
        for (int i = 0; i < 4; i++)
            asm volatile("mbarrier.init.shared.b64 [%0], 1;" :: "r"(sb + 24 + 8 * i) : "memory");
    }
    if (wid == 0)
        asm volatile("tcgen05.alloc.cta_group::1.sync.aligned.shared::cta.b32 [%0], %1;"
                     :: "r"(sb), "r"(512u) : "memory");
    __syncthreads();
    uint32_t tb = *(volatile uint32_t*)smem;

    // kick off async fills: A image, W0, W1 (if any)
    if (tid == 0) {
        bulk_cp(sb + SG_A, Aimg + (size_t)blockIdx.x * 65536, 65536, sb + 24);
        bulk_cp(sb + SG_W0, (const uint8_t*)g_wt + (size_t)wi0 * 65536, 65536, sb + 32);
        if (nl > 1)
            bulk_cp(sb + SG_W0 + 65536, (const uint8_t*)g_wt + (size_t)wi1 * 65536, 65536, sb + 40);
    }

    const int wis2 = wi2;
    float* const outp[3] = {o0, o1, o2};

    for (int i = 0; i < nl; i++) {
        asm volatile("tcgen05.fence::after_thread_sync;" ::: "memory");
        if (wid == 0 && elect1()) {
            if (i == 0) mbar_waitp(sb + 24, 0);       // A image ready
            mbar_waitp(sb + 32 + 8 * i, 0);           // W_i ready
            issue_mma3(sb, SG_A, SG_W0 + (uint32_t)(i & 1) * 65536, tb + (i & 1) * 128);
            asm volatile(
                "tcgen05.commit.cta_group::1.mbarrier::arrive::one.shared::cluster.b64 [%0];"
                :: "r"(sb + 8 + (i & 1) * 8) : "memory");
        }
        if (i > 0)   // epilogue of previous layer overlaps this layer's MMA + W prefetch
            ep_store_global(tb + ((i - 1) & 1) * 128, outp[i - 1], (bvmask >> (i - 1)) & 1,
                            row0, nrows, wid, lid);
        mbar_waitp(sb + 8 + (i & 1) * 8, (uint32_t)(i >> 1));   // MMA_i done
        if (tid == 0 && i + 2 < nl)   // W_{i+2} into buf[i&1] (now free)
            bulk_cp(sb + SG_W0 + (uint32_t)(i & 1) * 65536,
                    (const uint8_t*)g_wt + (size_t)wis2 * 65536, 65536, sb + 32 + 8 * (i + 2));
        __syncthreads();   // all warps past epilogue LDTM before TMEM buffer reuse
    }
    asm volatile("tcgen05.fence::after_thread_sync;" ::: "memory");
    ep_store_global(tb + ((nl - 1) & 1) * 128, outp[nl - 1], (bvmask >> (nl - 1)) & 1,
                    row0, nrows, wid, lid);

    __syncthreads();
    if (wid == 0) {
        asm volatile("tcgen05.relinquish_alloc_permit.cta_group::1.sync.aligned;");
        asm volatile("tcgen05.dealloc.cta_group::1.sync.aligned.b32 %0, %1;" :: "r"(tb), "r"(512u));
    }
#endif
}

// ---------------- fused F-chain kernel ----------------
// net CTAs (blockIdx < gbn):  out_net = relu(C+ (relu(C+ relu(C+G0@W)@W) + G2)@W)
// cell CTAs: out_cell = relu(C + relu(C + (relu(C)+G1)@W)@W)      (C includes bvec)
// smem: A hi/lo 64KB, W (Wlb) 64KB, C fp32 tile padded stride 129 (66048 B)
#define SMC_A 1024
#define SMC_W (1024 + 65536)
#define SMC_C (1024 + 131072)
#define SMC_TOTAL (1024 + 131072 + 66048)

__global__ __launch_bounds__(256, 1) void chain_k(float* __restrict__ out, int nrows, int gbn) {
#if HAS_TCGEN05
    extern __shared__ char smem[];
    uint32_t sb = smem_u32(smem);
    int tid = threadIdx.x, wid = tid >> 5, lid = tid & 31;
    int isNet = blockIdx.x < gbn;
    int row0 = (isNet ? blockIdx.x : blockIdx.x - gbn) * 128;

    if (tid == 0)
        asm volatile("mbarrier.init.shared.b64 [%0], 1;" :: "r"(sb + 8) : "memory");
    if (wid == 0)
        asm volatile("tcgen05.alloc.cta_group::1.sync.aligned.shared::cta.b32 [%0], %1;"
                     :: "r"(sb), "r"(512u) : "memory");
    __syncthreads();
    uint32_t tb = *(volatile uint32_t*)smem;

    const float* Cg = isNet ? g_c_net : g_c_cell;
    float* Cs = (float*)(smem + SMC_C);
#pragma unroll
    for (int q0 = 0; q0 < 16; q0++) {
        int q = tid + q0 * 256;
        int row = q >> 5, k = (q & 31) << 2;
        int gr = row0 + row;
        float4 v = make_float4(0.f, 0.f, 0.f, 0.f);
        if (gr < nrows) v = *(const float4*)(Cg + (size_t)gr * D + k);
        Cs[row * 129 + k] = v.x; Cs[row * 129 + k + 1] = v.y;
        Cs[row * 129 + k + 2] = v.z; Cs[row * 129 + k + 3] = v.w;
    }
    if (isNet) load_split_A(g_G0, nullptr, 0, row0, nrows, smem + SMC_A, tid);
    else       load_split_A(g_c_cell, g_G1, 1, row0, nrows, smem + SMC_A, tid);
    copy_w(g_wt + 1 * 32768, smem + SMC_W, tid);   // Wlb
    asm volatile("fence.proxy.async.shared::cta;" ::: "memory");
    __syncthreads();

    int nl = isNet ? 3 : 2;
    int colb = (wid >> 2) * 64;
    int rloc = (wid & 3) * 32 + lid;
    int gr = row0 + rloc;

    for (int l = 0; l < nl; l++) {
        asm volatile("tcgen05.fence::after_thread_sync;" ::: "memory");
        if (wid == 0 && elect1()) {
            issue_mma3(sb, SMC_A, SMC_W, tb);
            asm volatile(
                "tcgen05.commit.cta_group::1.mbarrier::arrive::one.shared::cluster.b64 [%0];"
                :: "r"(sb + 8) : "memory");
        }
        mbar_waitp(sb + 8, (uint32_t)(l & 1));
        asm volatile("tcgen05.fence::after_thread_sync;" ::: "memory");

        uint32_t dr[64];
        tmem_ld_x32(dr, tb + colb);
        tmem_ld_x32(dr + 32, tb + colb + 32);
        asm volatile("tcgen05.wait::ld.sync.aligned;" ::: "memory");

        float o[64];
#pragma unroll
        for (int j = 0; j < 64; j++) {
            float v = __uint_as_float(dr[j]) + Cs[rloc * 129 + colb + j];
            o[j] = v > 0.f ? v : 0.f;
        }
        if (l == nl - 1) {
            if (gr < nrows) {
                float4* dp = (float4*)(out + (size_t)(isNet ? gr : nrows + gr) * D + colb);
#pragma unroll
                for (int j = 0; j < 16; j++)
                    dp[j] = make_float4(o[j * 4], o[j * 4 + 1], o[j * 4 + 2], o[j * 4 + 3]);
            }
            asm volatile("tcgen05.fence::before_thread_sync;" ::: "memory");
        } else {
            if (isNet && l == 1 && gr < nrows) {   // add G2 before final layer
                const float4* g2 = (const float4*)(g_G2 + (size_t)gr * D + colb);
#pragma unroll
                for (int j = 0; j < 16; j++) {
                    float4 u = g2[j];
                    o[j * 4] += u.x; o[j * 4 + 1] += u.y; o[j * 4 + 2] += u.z; o[j * 4 + 3] += u.w;
                }
            }
#pragma unroll
            for (int j = 0; j < 16; j++) {
                float4 v = make_float4(o[j * 4], o[j * 4 + 1], o[j * 4 + 2], o[j * 4 + 3]);
                uint2 hi, lo;
                split4(v, hi, lo);
                int chunk = colb >> 6;
                uint32_t bo = rloc * 128 + (j * 4) * 2;
                uint32_t sw = bo ^ ((bo >> 3) & 0x70);
                *(uint2*)(smem + SMC_A + chunk * 16384 + sw) = hi;
                *(uint2*)(smem + SMC_A + chunk * 16384 + 32768 + sw) = lo;
            }
            asm volatile("fence.proxy.async.shared::cta;" ::: "memory");
            asm volatile("tcgen05.fence::before_thread_sync;" ::: "memory");
            __syncthreads();
        }
    }

    __syncthreads();
    if (wid == 0) {
        asm volatile("tcgen05.relinquish_alloc_permit.cta_group::1.sync.aligned;");
        asm volatile("tcgen05.dealloc.cta_group::1.sync.aligned.b32 %0, %1;" :: "r"(tb), "r"(512u));
    }
#endif
}

// ---------------- host launch ----------------
extern "C" void kernel_launch(void* const* d_in, const int* in_sizes, int n_in,
                              void* d_out, int out_size) {
    const float* x_net   = (const float*)d_in[0];
    const float* x_cell  = (const float*)d_in[1];
    const float* Wp_net  = (const float*)d_in[2];
    const float* Wp_cell = (const float*)d_in[3];
    const float* Wg0 = (const float*)d_in[4];
    const float* al0 = (const float*)d_in[5];
    const float* ar0 = (const float*)d_in[6];
    const float* Wg1 = (const float*)d_in[7];
    const float* al1 = (const float*)d_in[8];
    const float* ar1 = (const float*)d_in[9];
    const float* Wg2 = (const float*)d_in[10];
    const float* al2 = (const float*)d_in[11];
    const float* ar2 = (const float*)d_in[12];
    const float* Wl   = (const float*)d_in[13];
    const float* bias = (const float*)d_in[14];
    const int* src0 = (const int*)d_in[15];
    const int* dst0 = (const int*)d_in[16];
    const int* src1 = (const int*)d_in[17];
    const int* dst1 = (const int*)d_in[18];
    const int* src2 = (const int*)d_in[19];
    const int* dst2 = (const int*)d_in[20];

    int n  = in_sizes[0] / DIN;
    int E0 = in_sizes[15], E1 = in_sizes[17], E2 = in_sizes[19];
    float* out = (float*)d_out;
    int gb = (n + 127) / 128;
    int nwpt = gb * 4;           // warps per node type (covers full tile padding)
    int Et = E0 + E1 + E2;

    float *se0, *se1, *se2, *dn0, *dn1, *dn2, *hs0, *hs1, *hs2, *G0, *G1, *G2;
    float *c_net, *c_cell;
    uint8_t *himg_n, *himg_c;
    cudaGetSymbolAddress((void**)&se0, g_se0);
    cudaGetSymbolAddress((void**)&se1, g_se1);
    cudaGetSymbolAddress((void**)&se2, g_se2);
    cudaGetSymbolAddress((void**)&dn0, g_dn0);
    cudaGetSymbolAddress((void**)&dn1, g_dn1);
    cudaGetSymbolAddress((void**)&dn2, g_dn2);
    cudaGetSymbolAddress((void**)&hs0, g_hsrc0);
    cudaGetSymbolAddress((void**)&hs1, g_hsrc1);
    cudaGetSymbolAddress((void**)&hs2, g_hsrc2);
    cudaGetSymbolAddress((void**)&G0, g_G0);
    cudaGetSymbolAddress((void**)&G1, g_G1);
    cudaGetSymbolAddress((void**)&G2, g_G2);
    cudaGetSymbolAddress((void**)&c_net, g_c_net);
    cudaGetSymbolAddress((void**)&c_cell, g_c_cell);
    cudaGetSymbolAddress((void**)&himg_n, g_himg_net);
    cudaGetSymbolAddress((void**)&himg_c, g_himg_cell);

    cudaFuncSetAttribute(gemm35_k, cudaFuncAttributeMaxDynamicSharedMemorySize, SG_TOTAL);
    cudaFuncSetAttribute(chain_k, cudaFuncAttributeMaxDynamicSharedMemorySize, SMC_TOTAL);

    vecprep_k<<<1, 128>>>(Wg0, al0, ar0, Wg1, al1, ar1, Wg2, al2, ar2, Wl, bias,
                          Wp_net, Wp_cell);                                             // 1
    wprep_all_k<<<(5 * 16384 + 255) / 256, 256>>>(Wl, Wg0, Wg1, Wg2);                   // 2
    projlog_k<<<(2 * nwpt + 7) / 8, 256>>>(x_net, x_cell, Wp_net, Wp_cell, n, nwpt);    // 3
    edge12m_k<<<(Et + 255) / 256, 256>>>(src0, dst0, src1, dst1, src2, dst2,
                                         E0, E1, E2);                                   // 4
    // cell GEMMs (2 layers: Wla->c_cell+bv, Wg0->hsrc0)
    gemm35_k<<<gb, 256, SG_TOTAL>>>(himg_c, 2, 0, 2, 0,
                                    c_cell, hs0, nullptr, 0x1, n);                      // 5
    edge3_k<<<(E0 * 32 + 255) / 256, 256>>>(src0, dst0, se0, dn0, hs0, G0, E0);         // 6 <- profiled
    // net GEMMs (3 layers: Wla->c_net+bv, Wg1->hsrc1, Wg2->hsrc2)
    gemm35_k<<<gb, 256, SG_TOTAL>>>(himg_n, 3, 0, 3, 4,
                                    c_net, hs1, hs2, 0x1, n);                           // 7
    edge3_k<<<(E1 * 32 + 255) / 256, 256>>>(src1, dst1, se1, dn1, hs1, G1, E1);         // 8
    edge3_k<<<(E2 * 32 + 255) / 256, 256>>>(src2, dst2, se2, dn2, hs2, G2, E2);         // 9
    chain_k<<<2 * gb, 256, SMC_TOTAL>>>(out, n, gb);                                    // 10
}